// round 1
// baseline (speedup 1.0000x reference)
#include <cuda_runtime.h>
#include <cuda_bf16.h>

#define N_NODES 50000
#define N_EDGES 800000
#define N_GRAPHS 1024
#define HDIM 128
#define NLAYERS 5

// ---------------- scratch (device globals; no allocation allowed) ----------------
__device__ float g_x[N_NODES * HDIM];        // node features
__device__ float g_e[N_EDGES * HDIM];        // edge features (fixed across layers)
__device__ float g_xw[N_NODES * 256];        // x @ W1[:128] + b1
__device__ float g_m1[N_EDGES * 256];        // silu(e@W1[128:] + xw[src])
__device__ float g_aggr[N_NODES * HDIM];     // scatter accumulator
__device__ float g_cnt[N_NODES];             // in-degree
__device__ float g_pool[N_GRAPHS * HDIM];
__device__ float g_gcnt[N_GRAPHS];

__device__ __forceinline__ float silu_f(float v) { return v / (1.0f + __expf(-v)); }

// block = 128 threads (4 warps). Computes mean/var of per-thread value v over the block.
__device__ __forceinline__ void ln_stats128(float v, float& mean, float& var,
                                            float* s1, float* s2) {
    float a = v, b = v * v;
    #pragma unroll
    for (int o = 16; o > 0; o >>= 1) {
        a += __shfl_down_sync(0xffffffffu, a, o);
        b += __shfl_down_sync(0xffffffffu, b, o);
    }
    int w = threadIdx.x >> 5;
    if ((threadIdx.x & 31) == 0) { s1[w] = a; s2[w] = b; }
    __syncthreads();
    if (threadIdx.x == 0) {
        s1[0] = s1[0] + s1[1] + s1[2] + s1[3];
        s2[0] = s2[0] + s2[1] + s2[2] + s2[3];
    }
    __syncthreads();
    mean = s1[0] * (1.0f / 128.0f);
    var  = s2[0] * (1.0f / 128.0f) - mean * mean;
}

// ---------------- node embedding: x = silu(LN(atom @ emb_w + emb_b)) ----------------
__global__ __launch_bounds__(128) void k_node_embed(
    const float* __restrict__ atom, const float* __restrict__ w,
    const float* __restrict__ b, const float* __restrict__ lg,
    const float* __restrict__ lb, float* __restrict__ x)
{
    __shared__ float s1[4], s2[4], sa[4];
    int n = blockIdx.x, h = threadIdx.x;
    if (h < 4) sa[h] = atom[n * 4 + h];
    __syncthreads();
    float v = b[h];
    #pragma unroll
    for (int k = 0; k < 4; k++) v = fmaf(sa[k], __ldg(&w[k * 128 + h]), v);
    float mean, var;
    ln_stats128(v, mean, var, s1, s2);
    float y = (v - mean) * rsqrtf(var + 1e-5f) * lg[h] + lb[h];
    x[n * 128 + h] = silu_f(y);
}

// ---------------- edge embedding: e = silu(nbr @ edge_w + edge_b), K=41 ----------------
__global__ __launch_bounds__(128) void k_edge_embed(
    const float* __restrict__ nbr, const float* __restrict__ w,
    const float* __restrict__ b, float* __restrict__ e)
{
    __shared__ float snbr[64][42];
    const int h = threadIdx.x;
    const long e0 = (long)blockIdx.x * 64;
    float wr[41];
    #pragma unroll
    for (int k = 0; k < 41; k++) wr[k] = w[k * 128 + h];
    const float* base = nbr + e0 * 41;
    for (int t = h; t < 64 * 41; t += 128) snbr[t / 41][t % 41] = base[t];
    float bb = b[h];
    __syncthreads();
    for (int r = 0; r < 64; r++) {
        float acc = bb;
        #pragma unroll
        for (int k = 0; k < 41; k++) acc = fmaf(snbr[r][k], wr[k], acc);
        e[(e0 + r) * 128 + h] = silu_f(acc);
    }
}

// ---------------- degree count ----------------
__global__ void k_cnt(const int* __restrict__ idx, float* __restrict__ cnt, int nE) {
    int i = blockIdx.x * blockDim.x + threadIdx.x;
    if (i < nE) atomicAdd(&cnt[idx[2 * i + 1]], 1.0f);
}

// ---------------- SGEMM with fused epilogues ----------------
// EPI 0: C = A@B + bias                  (XW = x @ W1a + b1)
// EPI 1: C = silu(A@B + rowadd[idx[row]])  (M1 = silu(e@W1b + XW[src]))
// EPI 2: atomicAdd scatter[idx[row]] += silu(A@B + bias)   (aggr)
template <int EPI>
__global__ __launch_bounds__(256) void sgemm_k(
    const float* __restrict__ A, const float* __restrict__ B,
    float* __restrict__ C, int M, int N, int K,
    const float* __restrict__ bias, const float* __restrict__ rowadd,
    const int* __restrict__ idx, int idxStride, int idxOff,
    float* __restrict__ scatter)
{
    constexpr int BM = 128, BN = 128, BK = 16, TM = 8, TN = 8;
    __shared__ float As[BK][BM];
    __shared__ float Bs[BK][BN];
    const int tid = threadIdx.x;
    const int tx = tid & 15, ty = tid >> 4;
    const long rowBase = (long)blockIdx.y * BM;
    const int colBase = blockIdx.x * BN;

    const int aR = tid >> 2;          // 0..63
    const int aK = (tid & 3) << 2;    // 0,4,8,12
    const int bR = tid >> 5;          // 0..7
    const int bC = (tid & 31) << 2;   // 0..124

    float acc[TM][TN];
    #pragma unroll
    for (int i = 0; i < TM; i++)
        #pragma unroll
        for (int j = 0; j < TN; j++) acc[i][j] = 0.0f;

    for (int kk = 0; kk < K; kk += BK) {
        #pragma unroll
        for (int hh = 0; hh < 2; hh++) {
            int r = aR + hh * 64;
            long gr = rowBase + r;
            float4 v = make_float4(0.f, 0.f, 0.f, 0.f);
            if (gr < M) v = *reinterpret_cast<const float4*>(&A[gr * K + kk + aK]);
            As[aK + 0][r] = v.x; As[aK + 1][r] = v.y;
            As[aK + 2][r] = v.z; As[aK + 3][r] = v.w;
        }
        #pragma unroll
        for (int hh = 0; hh < 2; hh++) {
            int r = bR + hh * 8;
            *reinterpret_cast<float4*>(&Bs[r][bC]) =
                *reinterpret_cast<const float4*>(&B[(long)(kk + r) * N + colBase + bC]);
        }
        __syncthreads();
        #pragma unroll
        for (int k = 0; k < BK; k++) {
            float ra[TM], rb[TN];
            #pragma unroll
            for (int i = 0; i < TM; i += 4)
                *reinterpret_cast<float4*>(&ra[i]) =
                    *reinterpret_cast<const float4*>(&As[k][ty * TM + i]);
            #pragma unroll
            for (int j = 0; j < TN; j += 4)
                *reinterpret_cast<float4*>(&rb[j]) =
                    *reinterpret_cast<const float4*>(&Bs[k][tx * TN + j]);
            #pragma unroll
            for (int i = 0; i < TM; i++)
                #pragma unroll
                for (int j = 0; j < TN; j++)
                    acc[i][j] = fmaf(ra[i], rb[j], acc[i][j]);
        }
        __syncthreads();
    }

    const int cb = colBase + tx * TN;
    float bb[TN];
    if (EPI == 0 || EPI == 2) {
        #pragma unroll
        for (int j = 0; j < TN; j++) bb[j] = bias[cb + j];
    }
    #pragma unroll
    for (int i = 0; i < TM; i++) {
        long gr = rowBase + ty * TM + i;
        if (gr >= M) continue;
        if (EPI == 0) {
            float4 o;
            o.x = acc[i][0] + bb[0]; o.y = acc[i][1] + bb[1];
            o.z = acc[i][2] + bb[2]; o.w = acc[i][3] + bb[3];
            *reinterpret_cast<float4*>(&C[gr * N + cb]) = o;
            o.x = acc[i][4] + bb[4]; o.y = acc[i][5] + bb[5];
            o.z = acc[i][6] + bb[6]; o.w = acc[i][7] + bb[7];
            *reinterpret_cast<float4*>(&C[gr * N + cb + 4]) = o;
        } else if (EPI == 1) {
            int s = idx[gr * idxStride + idxOff];
            const float4* rp = reinterpret_cast<const float4*>(rowadd + (long)s * N + cb);
            float4 v0 = rp[0], v1 = rp[1];
            float4 o0, o1;
            o0.x = silu_f(acc[i][0] + v0.x); o0.y = silu_f(acc[i][1] + v0.y);
            o0.z = silu_f(acc[i][2] + v0.z); o0.w = silu_f(acc[i][3] + v0.w);
            o1.x = silu_f(acc[i][4] + v1.x); o1.y = silu_f(acc[i][5] + v1.y);
            o1.z = silu_f(acc[i][6] + v1.z); o1.w = silu_f(acc[i][7] + v1.w);
            *reinterpret_cast<float4*>(&C[gr * N + cb])     = o0;
            *reinterpret_cast<float4*>(&C[gr * N + cb + 4]) = o1;
        } else {
            int d = idx[gr * idxStride + idxOff];
            float* sp = scatter + (long)d * N + cb;
            #pragma unroll
            for (int j = 0; j < TN; j++)
                atomicAdd(&sp[j], silu_f(acc[i][j] + bb[j]));
        }
    }
}

// ---------------- x = LN(x + aggr/cnt) ----------------
__global__ __launch_bounds__(128) void k_ln_aggr(
    float* __restrict__ x, const float* __restrict__ aggr,
    const float* __restrict__ cnt, const float* __restrict__ lg,
    const float* __restrict__ lb)
{
    __shared__ float s1[4], s2[4];
    int n = blockIdx.x, h = threadIdx.x;
    float c = cnt[n]; if (c < 1.0f) c = 1.0f;
    float t = x[n * 128 + h] + aggr[n * 128 + h] / c;
    float mean, var;
    ln_stats128(t, mean, var, s1, s2);
    x[n * 128 + h] = (t - mean) * rsqrtf(var + 1e-5f) * lg[h] + lb[h];
}

// ---------------- graph pooling ----------------
__global__ __launch_bounds__(128) void k_pool(
    const float* __restrict__ x, const int* __restrict__ bm,
    float* __restrict__ pool, float* __restrict__ gcnt)
{
    int n = blockIdx.x, h = threadIdx.x;
    int g = bm[n];
    atomicAdd(&pool[g * 128 + h], x[n * 128 + h]);
    if (h == 0) atomicAdd(&gcnt[g], 1.0f);
}

// ---------------- output MLP ----------------
__global__ __launch_bounds__(128) void k_head(
    const float* __restrict__ pool, const float* __restrict__ gcnt,
    const float* __restrict__ w1, const float* __restrict__ b1,
    const float* __restrict__ w2, const float* __restrict__ b2,
    const float* __restrict__ w3, const float* __restrict__ b3,
    float* __restrict__ out)
{
    __shared__ float c[128], h1[128], h2[64];
    int g = blockIdx.x, h = threadIdx.x;
    float gc = gcnt[g]; if (gc < 1.0f) gc = 1.0f;
    c[h] = pool[g * 128 + h] / gc;
    __syncthreads();
    float a = b1[h];
    #pragma unroll 8
    for (int k = 0; k < 128; k++) a = fmaf(c[k], __ldg(&w1[k * 128 + h]), a);
    h1[h] = silu_f(a);
    __syncthreads();
    if (h < 64) {
        float a2 = b2[h];
        #pragma unroll 8
        for (int k = 0; k < 128; k++) a2 = fmaf(h1[k], __ldg(&w2[k * 64 + h]), a2);
        h2[h] = silu_f(a2);
    }
    __syncthreads();
    if (h < 3) {
        float a3 = b3[h];
        #pragma unroll
        for (int k = 0; k < 64; k++) a3 = fmaf(h2[k], __ldg(&w3[k * 3 + h]), a3);
        out[g * 3 + h] = a3;
    }
}

static inline int ceildiv(int a, int b) { return (a + b - 1) / b; }

extern "C" void kernel_launch(void* const* d_in, const int* in_sizes, int n_in,
                              void* d_out, int out_size)
{
    const float* atom_fea = (const float*)d_in[0];
    const float* nbr_fea  = (const float*)d_in[1];
    const int*   nbr_idx  = (const int*)  d_in[2];
    const int*   batch    = (const int*)  d_in[3];
    const float* emb_w    = (const float*)d_in[4];
    const float* emb_b    = (const float*)d_in[5];
    const float* emb_ln_g = (const float*)d_in[6];
    const float* emb_ln_b = (const float*)d_in[7];
    const float* edge_w   = (const float*)d_in[8];
    const float* edge_b   = (const float*)d_in[9];
    const float* conv_w1  = (const float*)d_in[10];
    const float* conv_b1  = (const float*)d_in[11];
    const float* conv_w2  = (const float*)d_in[12];
    const float* conv_b2  = (const float*)d_in[13];
    const float* ln_g     = (const float*)d_in[14];
    const float* ln_b     = (const float*)d_in[15];
    const float* out_w1   = (const float*)d_in[16];
    const float* out_b1   = (const float*)d_in[17];
    const float* out_w2   = (const float*)d_in[18];
    const float* out_b2   = (const float*)d_in[19];
    const float* out_w3   = (const float*)d_in[20];
    const float* out_b3   = (const float*)d_in[21];
    float* out = (float*)d_out;

    float *x, *e, *xw, *m1, *aggr, *cnt, *pool, *gcnt;
    cudaGetSymbolAddress((void**)&x,    g_x);
    cudaGetSymbolAddress((void**)&e,    g_e);
    cudaGetSymbolAddress((void**)&xw,   g_xw);
    cudaGetSymbolAddress((void**)&m1,   g_m1);
    cudaGetSymbolAddress((void**)&aggr, g_aggr);
    cudaGetSymbolAddress((void**)&cnt,  g_cnt);
    cudaGetSymbolAddress((void**)&pool, g_pool);
    cudaGetSymbolAddress((void**)&gcnt, g_gcnt);

    cudaMemsetAsync(cnt,  0, N_NODES * sizeof(float), 0);
    cudaMemsetAsync(pool, 0, N_GRAPHS * HDIM * sizeof(float), 0);
    cudaMemsetAsync(gcnt, 0, N_GRAPHS * sizeof(float), 0);

    k_node_embed<<<N_NODES, 128>>>(atom_fea, emb_w, emb_b, emb_ln_g, emb_ln_b, x);
    k_edge_embed<<<N_EDGES / 64, 128>>>(nbr_fea, edge_w, edge_b, e);
    k_cnt<<<ceildiv(N_EDGES, 256), 256>>>(nbr_idx, cnt, N_EDGES);

    for (int i = 0; i < NLAYERS; i++) {
        const float* W1a = conv_w1 + (long)i * 256 * 256;            // rows 0..127
        const float* W1b = W1a + 128 * 256;                           // rows 128..255
        const float* W2  = conv_w2 + (long)i * 256 * 128;
        const float* b1  = conv_b1 + (long)i * 256;
        const float* b2  = conv_b2 + (long)i * 128;

        // XW = x @ W1a + b1   [50000, 256]
        sgemm_k<0><<<dim3(2, ceildiv(N_NODES, 128)), 256>>>(
            x, W1a, xw, N_NODES, 256, 128, b1, nullptr, nullptr, 0, 0, nullptr);
        // M1 = silu(e @ W1b + XW[src])   [800000, 256]
        sgemm_k<1><<<dim3(2, N_EDGES / 128), 256>>>(
            e, W1b, m1, N_EDGES, 256, 128, nullptr, xw, nbr_idx, 2, 0, nullptr);
        cudaMemsetAsync(aggr, 0, N_NODES * HDIM * sizeof(float), 0);
        // aggr[dst] += silu(M1 @ W2 + b2)
        sgemm_k<2><<<dim3(1, N_EDGES / 128), 256>>>(
            m1, W2, nullptr, N_EDGES, 128, 256, b2, nullptr, nbr_idx, 2, 1, aggr);
        // x = LN(x + aggr/cnt)
        k_ln_aggr<<<N_NODES, 128>>>(x, aggr, cnt, ln_g + i * 128, ln_b + i * 128);
    }

    k_pool<<<N_NODES, 128>>>(x, batch, pool, gcnt);
    k_head<<<N_GRAPHS, 128>>>(pool, gcnt, out_w1, out_b1, out_w2, out_b2,
                              out_w3, out_b3, out);
    (void)in_sizes; (void)n_in; (void)out_size;
}

// round 2
// speedup vs baseline: 3.1215x; 3.1215x over previous
#include <cuda_runtime.h>
#include <cuda_fp16.h>
#include <cuda_bf16.h>
#include <cstdint>

#define N_NODES 50000
#define N_EDGES 800000
#define N_GRAPHS 1024
#define HDIM 128
#define NLAYERS 5

// ---------------- scratch (device globals; no allocation allowed) ----------------
__device__ float  g_x[N_NODES * HDIM];        // node features (fp32)
__device__ __half g_eh[N_EDGES * HDIM];       // edge features fp16 (fixed across layers)
__device__ float  g_xw[N_NODES * 256];        // x @ W1[:128] + b1 (fp32)
__device__ float  g_aggr[N_NODES * HDIM];     // scatter accumulator
__device__ float  g_cnt[N_NODES];             // in-degree
__device__ float  g_pool[N_GRAPHS * HDIM];
__device__ float  g_gcnt[N_GRAPHS];
__device__ __half g_w1h[128 * 256];           // W1b fp16 (per-layer)
__device__ __half g_w2h[256 * 128];           // W2  fp16 (per-layer)

__device__ __forceinline__ float silu_f(float v) { return v / (1.0f + __expf(-v)); }

__device__ __forceinline__ uint32_t sptr(const void* p) {
    return (uint32_t)__cvta_generic_to_shared(p);
}

__device__ __forceinline__ void ldsm_x4(uint32_t* r, uint32_t addr) {
    asm volatile("ldmatrix.sync.aligned.m8n8.x4.shared.b16 {%0,%1,%2,%3}, [%4];\n"
                 : "=r"(r[0]), "=r"(r[1]), "=r"(r[2]), "=r"(r[3]) : "r"(addr));
}
__device__ __forceinline__ void ldsm_x4_t(uint32_t* r, uint32_t addr) {
    asm volatile("ldmatrix.sync.aligned.m8n8.x4.trans.shared.b16 {%0,%1,%2,%3}, [%4];\n"
                 : "=r"(r[0]), "=r"(r[1]), "=r"(r[2]), "=r"(r[3]) : "r"(addr));
}
__device__ __forceinline__ void mma_16816(float* c, const uint32_t* a, const uint32_t* b) {
    asm volatile(
        "mma.sync.aligned.m16n8k16.row.col.f32.f16.f16.f32 "
        "{%0,%1,%2,%3}, {%4,%5,%6,%7}, {%8,%9}, {%0,%1,%2,%3};\n"
        : "+f"(c[0]), "+f"(c[1]), "+f"(c[2]), "+f"(c[3])
        : "r"(a[0]), "r"(a[1]), "r"(a[2]), "r"(a[3]), "r"(b[0]), "r"(b[1]));
}

// block = 128 threads (4 warps). mean/var over the block.
__device__ __forceinline__ void ln_stats128(float v, float& mean, float& var,
                                            float* s1, float* s2) {
    float a = v, b = v * v;
    #pragma unroll
    for (int o = 16; o > 0; o >>= 1) {
        a += __shfl_down_sync(0xffffffffu, a, o);
        b += __shfl_down_sync(0xffffffffu, b, o);
    }
    int w = threadIdx.x >> 5;
    if ((threadIdx.x & 31) == 0) { s1[w] = a; s2[w] = b; }
    __syncthreads();
    if (threadIdx.x == 0) {
        s1[0] = s1[0] + s1[1] + s1[2] + s1[3];
        s2[0] = s2[0] + s2[1] + s2[2] + s2[3];
    }
    __syncthreads();
    mean = s1[0] * (1.0f / 128.0f);
    var  = s2[0] * (1.0f / 128.0f) - mean * mean;
}

// ---------------- node embedding ----------------
__global__ __launch_bounds__(128) void k_node_embed(
    const float* __restrict__ atom, const float* __restrict__ w,
    const float* __restrict__ b, const float* __restrict__ lg,
    const float* __restrict__ lb, float* __restrict__ x)
{
    __shared__ float s1[4], s2[4], sa[4];
    int n = blockIdx.x, h = threadIdx.x;
    if (h < 4) sa[h] = atom[n * 4 + h];
    __syncthreads();
    float v = b[h];
    #pragma unroll
    for (int k = 0; k < 4; k++) v = fmaf(sa[k], __ldg(&w[k * 128 + h]), v);
    float mean, var;
    ln_stats128(v, mean, var, s1, s2);
    float y = (v - mean) * rsqrtf(var + 1e-5f) * lg[h] + lb[h];
    x[n * 128 + h] = silu_f(y);
}

// ---------------- edge embedding: e = silu(nbr @ edge_w + edge_b) -> fp16 ----------------
__global__ __launch_bounds__(128) void k_edge_embed(
    const float* __restrict__ nbr, const float* __restrict__ w,
    const float* __restrict__ b, __half* __restrict__ e)
{
    __shared__ float snbr[64][42];
    const int h = threadIdx.x;
    const long e0 = (long)blockIdx.x * 64;
    float wr[41];
    #pragma unroll
    for (int k = 0; k < 41; k++) wr[k] = w[k * 128 + h];
    const float* base = nbr + e0 * 41;
    for (int t = h; t < 64 * 41; t += 128) snbr[t / 41][t % 41] = base[t];
    float bb = b[h];
    __syncthreads();
    for (int r = 0; r < 64; r++) {
        float acc = bb;
        #pragma unroll
        for (int k = 0; k < 41; k++) acc = fmaf(snbr[r][k], wr[k], acc);
        e[(e0 + r) * 128 + h] = __float2half_rn(silu_f(acc));
    }
}

// ---------------- degree count ----------------
__global__ void k_cnt(const int* __restrict__ idx, float* __restrict__ cnt, int nE) {
    int i = blockIdx.x * blockDim.x + threadIdx.x;
    if (i < nE) atomicAdd(&cnt[idx[2 * i + 1]], 1.0f);
}

// ---------------- per-layer weight conversion to fp16 ----------------
__global__ __launch_bounds__(512) void k_cvt(
    const float* __restrict__ w1b, const float* __restrict__ w2,
    __half* __restrict__ o1, __half* __restrict__ o2)
{
    int i = blockIdx.x * 512 + threadIdx.x;
    if (i < 32768) {
        o1[i] = __float2half_rn(w1b[i]);
        o2[i] = __float2half_rn(w2[i]);
    }
}

// ---------------- fp32 SGEMM (kept for XW = x @ W1a + b1) ----------------
__global__ __launch_bounds__(256) void sgemm_bias(
    const float* __restrict__ A, const float* __restrict__ B,
    float* __restrict__ C, int M, int N, int K, const float* __restrict__ bias)
{
    constexpr int BM = 128, BN = 128, BK = 16, TM = 8, TN = 8;
    __shared__ float As[BK][BM];
    __shared__ float Bs[BK][BN];
    const int tid = threadIdx.x;
    const int tx = tid & 15, ty = tid >> 4;
    const long rowBase = (long)blockIdx.y * BM;
    const int colBase = blockIdx.x * BN;
    const int aR = tid >> 2, aK = (tid & 3) << 2;
    const int bR = tid >> 5, bC = (tid & 31) << 2;

    float acc[TM][TN];
    #pragma unroll
    for (int i = 0; i < TM; i++)
        #pragma unroll
        for (int j = 0; j < TN; j++) acc[i][j] = 0.0f;

    for (int kk = 0; kk < K; kk += BK) {
        #pragma unroll
        for (int hh = 0; hh < 2; hh++) {
            int r = aR + hh * 64;
            long gr = rowBase + r;
            float4 v = make_float4(0.f, 0.f, 0.f, 0.f);
            if (gr < M) v = *reinterpret_cast<const float4*>(&A[gr * K + kk + aK]);
            As[aK + 0][r] = v.x; As[aK + 1][r] = v.y;
            As[aK + 2][r] = v.z; As[aK + 3][r] = v.w;
        }
        #pragma unroll
        for (int hh = 0; hh < 2; hh++) {
            int r = bR + hh * 8;
            *reinterpret_cast<float4*>(&Bs[r][bC]) =
                *reinterpret_cast<const float4*>(&B[(long)(kk + r) * N + colBase + bC]);
        }
        __syncthreads();
        #pragma unroll
        for (int k = 0; k < BK; k++) {
            float ra[TM], rb[TN];
            #pragma unroll
            for (int i = 0; i < TM; i += 4)
                *reinterpret_cast<float4*>(&ra[i]) =
                    *reinterpret_cast<const float4*>(&As[k][ty * TM + i]);
            #pragma unroll
            for (int j = 0; j < TN; j += 4)
                *reinterpret_cast<float4*>(&rb[j]) =
                    *reinterpret_cast<const float4*>(&Bs[k][tx * TN + j]);
            #pragma unroll
            for (int i = 0; i < TM; i++)
                #pragma unroll
                for (int j = 0; j < TN; j++)
                    acc[i][j] = fmaf(ra[i], rb[j], acc[i][j]);
        }
        __syncthreads();
    }
    const int cb = colBase + tx * TN;
    #pragma unroll
    for (int i = 0; i < TM; i++) {
        long gr = rowBase + ty * TM + i;
        if (gr >= M) continue;
        #pragma unroll
        for (int j = 0; j < TN; j += 4) {
            float4 o;
            o.x = acc[i][j + 0] + bias[cb + j + 0];
            o.y = acc[i][j + 1] + bias[cb + j + 1];
            o.z = acc[i][j + 2] + bias[cb + j + 2];
            o.w = acc[i][j + 3] + bias[cb + j + 3];
            *reinterpret_cast<float4*>(&C[gr * N + cb + j]) = o;
        }
    }
}

// ---------------- fused conv layer (tensor cores) ----------------
// Per block: 128 edges.
// Phase 1: M1 = silu(e @ W1b + xw[src])  -> smem (fp16), computed in two 128-col halves
// Phase 2: aggr[dst] += silu(M1 @ W2 + b2)  (atomics)
#define SM1_STRIDE 264
#define SA_STRIDE  56
#define SB_STRIDE  136
#define SMEM_SM1   (128 * SM1_STRIDE * 2)              // 67584
#define SMEM_SA    (128 * SA_STRIDE * 2)               // 14336
#define SMEM_SB    (32 * SB_STRIDE * 2)                // 8704
#define SMEM_IDX   (128 * 8)                           // 1024
#define SMEM_TOTAL (SMEM_SM1 + SMEM_SA + SMEM_SB + SMEM_IDX)  // 91648

__global__ __launch_bounds__(256) void k_conv_fused(
    const __half* __restrict__ E, const __half* __restrict__ W1b,
    const __half* __restrict__ W2, const float* __restrict__ XW,
    const float* __restrict__ b2, const int* __restrict__ idx,
    float* __restrict__ aggr)
{
    extern __shared__ char smem[];
    __half* sM1 = (__half*)smem;
    __half* sA  = (__half*)(smem + SMEM_SM1);
    __half* sB  = (__half*)(smem + SMEM_SM1 + SMEM_SA);
    int2*  sIdx = (int2*)(smem + SMEM_SM1 + SMEM_SA + SMEM_SB);

    const int tid  = threadIdx.x;
    const int lane = tid & 31;
    const int warp = tid >> 5;
    const int warp_m = (warp & 3) * 32;
    const int warp_n = (warp >> 2) * 64;
    const int g = lane >> 2, t = lane & 3;
    const long rowBase = (long)blockIdx.x * 128;

    if (tid < 128) sIdx[tid] = ((const int2*)idx)[rowBase + tid];

    const uint32_t sA_base  = sptr(sA);
    const uint32_t sB_base  = sptr(sB);
    const uint32_t sM1_base = sptr(sM1);

    float acc[2][8][4];

    // ================= Phase 1 =================
    #pragma unroll
    for (int nh = 0; nh < 2; nh++) {
        #pragma unroll
        for (int mi = 0; mi < 2; mi++)
            #pragma unroll
            for (int nj = 0; nj < 8; nj++)
                #pragma unroll
                for (int q = 0; q < 4; q++) acc[mi][nj][q] = 0.0f;

        for (int kk = 0; kk < 128; kk += 32) {
            __syncthreads();
            // load A tile: e rows [rowBase, +128), cols [kk, kk+32)
            #pragma unroll
            for (int p = 0; p < 2; p++) {
                int r = (tid >> 2) + p * 64;
                int q = (tid & 3) * 8;
                *(uint4*)&sA[r * SA_STRIDE + q] =
                    *(const uint4*)&E[(rowBase + r) * 128 + kk + q];
            }
            // load B tile: W1b rows [kk,kk+32), cols [nh*128, +128)
            #pragma unroll
            for (int p = 0; p < 2; p++) {
                int i2 = tid + p * 256;
                int r = i2 >> 4, q = (i2 & 15) * 8;
                *(uint4*)&sB[r * SB_STRIDE + q] =
                    *(const uint4*)&W1b[(kk + r) * 256 + nh * 128 + q];
            }
            __syncthreads();
            #pragma unroll
            for (int ks = 0; ks < 32; ks += 16) {
                uint32_t af[2][4], bf[8][2];
                #pragma unroll
                for (int mi = 0; mi < 2; mi++)
                    ldsm_x4(af[mi], sA_base +
                        ((warp_m + mi * 16 + (lane & 15)) * SA_STRIDE +
                         ks + (lane >> 4) * 8) * 2);
                #pragma unroll
                for (int np = 0; np < 4; np++) {
                    uint32_t r4[4];
                    ldsm_x4_t(r4, sB_base +
                        ((ks + (lane & 15)) * SB_STRIDE +
                         warp_n + np * 16 + (lane >> 4) * 8) * 2);
                    bf[np * 2 + 0][0] = r4[0]; bf[np * 2 + 0][1] = r4[1];
                    bf[np * 2 + 1][0] = r4[2]; bf[np * 2 + 1][1] = r4[3];
                }
                #pragma unroll
                for (int mi = 0; mi < 2; mi++)
                    #pragma unroll
                    for (int nj = 0; nj < 8; nj++)
                        mma_16816(acc[mi][nj], af[mi], bf[nj]);
            }
        }
        __syncthreads();
        // epilogue: add gathered xw, silu, store fp16 to sM1
        #pragma unroll
        for (int mi = 0; mi < 2; mi++) {
            int r0 = warp_m + mi * 16 + g;
            int r1 = r0 + 8;
            int s0 = sIdx[r0].x, s1 = sIdx[r1].x;
            #pragma unroll
            for (int nj = 0; nj < 8; nj++) {
                int col  = warp_n + nj * 8 + 2 * t;
                int gcol = nh * 128 + col;
                float2 x0 = *(const float2*)&XW[(long)s0 * 256 + gcol];
                float2 x1 = *(const float2*)&XW[(long)s1 * 256 + gcol];
                __half2 h0 = __floats2half2_rn(silu_f(acc[mi][nj][0] + x0.x),
                                               silu_f(acc[mi][nj][1] + x0.y));
                __half2 h1 = __floats2half2_rn(silu_f(acc[mi][nj][2] + x1.x),
                                               silu_f(acc[mi][nj][3] + x1.y));
                *(__half2*)&sM1[r0 * SM1_STRIDE + gcol] = h0;
                *(__half2*)&sM1[r1 * SM1_STRIDE + gcol] = h1;
            }
        }
    }

    // ================= Phase 2 =================
    #pragma unroll
    for (int mi = 0; mi < 2; mi++)
        #pragma unroll
        for (int nj = 0; nj < 8; nj++)
            #pragma unroll
            for (int q = 0; q < 4; q++) acc[mi][nj][q] = 0.0f;

    for (int kk = 0; kk < 256; kk += 32) {
        __syncthreads();
        // load B tile: W2 rows [kk,kk+32), cols [0,128)
        #pragma unroll
        for (int p = 0; p < 2; p++) {
            int i2 = tid + p * 256;
            int r = i2 >> 4, q = (i2 & 15) * 8;
            *(uint4*)&sB[r * SB_STRIDE + q] =
                *(const uint4*)&W2[(kk + r) * 128 + q];
        }
        __syncthreads();
        #pragma unroll
        for (int ks = 0; ks < 32; ks += 16) {
            uint32_t af[2][4], bf[8][2];
            #pragma unroll
            for (int mi = 0; mi < 2; mi++)
                ldsm_x4(af[mi], sM1_base +
                    ((warp_m + mi * 16 + (lane & 15)) * SM1_STRIDE +
                     kk + ks + (lane >> 4) * 8) * 2);
            #pragma unroll
            for (int np = 0; np < 4; np++) {
                uint32_t r4[4];
                ldsm_x4_t(r4, sB_base +
                    ((ks + (lane & 15)) * SB_STRIDE +
                     warp_n + np * 16 + (lane >> 4) * 8) * 2);
                bf[np * 2 + 0][0] = r4[0]; bf[np * 2 + 0][1] = r4[1];
                bf[np * 2 + 1][0] = r4[2]; bf[np * 2 + 1][1] = r4[3];
            }
            #pragma unroll
            for (int mi = 0; mi < 2; mi++)
                #pragma unroll
                for (int nj = 0; nj < 8; nj++)
                    mma_16816(acc[mi][nj], af[mi], bf[nj]);
        }
    }

    // epilogue: silu + bias, scatter-add to aggr[dst]
    float2 bb[8];
    #pragma unroll
    for (int nj = 0; nj < 8; nj++)
        bb[nj] = *(const float2*)&b2[warp_n + nj * 8 + 2 * t];
    #pragma unroll
    for (int mi = 0; mi < 2; mi++) {
        int r0 = warp_m + mi * 16 + g;
        int r1 = r0 + 8;
        long d0 = sIdx[r0].y, d1 = sIdx[r1].y;
        #pragma unroll
        for (int nj = 0; nj < 8; nj++) {
            int col = warp_n + nj * 8 + 2 * t;
            atomicAdd(&aggr[d0 * 128 + col],     silu_f(acc[mi][nj][0] + bb[nj].x));
            atomicAdd(&aggr[d0 * 128 + col + 1], silu_f(acc[mi][nj][1] + bb[nj].y));
            atomicAdd(&aggr[d1 * 128 + col],     silu_f(acc[mi][nj][2] + bb[nj].x));
            atomicAdd(&aggr[d1 * 128 + col + 1], silu_f(acc[mi][nj][3] + bb[nj].y));
        }
    }
}

// ---------------- x = LN(x + aggr/cnt) ----------------
__global__ __launch_bounds__(128) void k_ln_aggr(
    float* __restrict__ x, const float* __restrict__ aggr,
    const float* __restrict__ cnt, const float* __restrict__ lg,
    const float* __restrict__ lb)
{
    __shared__ float s1[4], s2[4];
    int n = blockIdx.x, h = threadIdx.x;
    float c = cnt[n]; if (c < 1.0f) c = 1.0f;
    float t = x[n * 128 + h] + aggr[n * 128 + h] / c;
    float mean, var;
    ln_stats128(t, mean, var, s1, s2);
    x[n * 128 + h] = (t - mean) * rsqrtf(var + 1e-5f) * lg[h] + lb[h];
}

// ---------------- graph pooling ----------------
__global__ __launch_bounds__(128) void k_pool(
    const float* __restrict__ x, const int* __restrict__ bm,
    float* __restrict__ pool, float* __restrict__ gcnt)
{
    int n = blockIdx.x, h = threadIdx.x;
    int g = bm[n];
    atomicAdd(&pool[g * 128 + h], x[n * 128 + h]);
    if (h == 0) atomicAdd(&gcnt[g], 1.0f);
}

// ---------------- output MLP ----------------
__global__ __launch_bounds__(128) void k_head(
    const float* __restrict__ pool, const float* __restrict__ gcnt,
    const float* __restrict__ w1, const float* __restrict__ b1,
    const float* __restrict__ w2, const float* __restrict__ b2,
    const float* __restrict__ w3, const float* __restrict__ b3,
    float* __restrict__ out)
{
    __shared__ float c[128], h1[128], h2[64];
    int g = blockIdx.x, h = threadIdx.x;
    float gc = gcnt[g]; if (gc < 1.0f) gc = 1.0f;
    c[h] = pool[g * 128 + h] / gc;
    __syncthreads();
    float a = b1[h];
    #pragma unroll 8
    for (int k = 0; k < 128; k++) a = fmaf(c[k], __ldg(&w1[k * 128 + h]), a);
    h1[h] = silu_f(a);
    __syncthreads();
    if (h < 64) {
        float a2 = b2[h];
        #pragma unroll 8
        for (int k = 0; k < 128; k++) a2 = fmaf(h1[k], __ldg(&w2[k * 64 + h]), a2);
        h2[h] = silu_f(a2);
    }
    __syncthreads();
    if (h < 3) {
        float a3 = b3[h];
        #pragma unroll
        for (int k = 0; k < 64; k++) a3 = fmaf(h2[k], __ldg(&w3[k * 3 + h]), a3);
        out[g * 3 + h] = a3;
    }
}

static inline int ceildiv(int a, int b) { return (a + b - 1) / b; }

extern "C" void kernel_launch(void* const* d_in, const int* in_sizes, int n_in,
                              void* d_out, int out_size)
{
    const float* atom_fea = (const float*)d_in[0];
    const float* nbr_fea  = (const float*)d_in[1];
    const int*   nbr_idx  = (const int*)  d_in[2];
    const int*   batch    = (const int*)  d_in[3];
    const float* emb_w    = (const float*)d_in[4];
    const float* emb_b    = (const float*)d_in[5];
    const float* emb_ln_g = (const float*)d_in[6];
    const float* emb_ln_b = (const float*)d_in[7];
    const float* edge_w   = (const float*)d_in[8];
    const float* edge_b   = (const float*)d_in[9];
    const float* conv_w1  = (const float*)d_in[10];
    const float* conv_b1  = (const float*)d_in[11];
    const float* conv_w2  = (const float*)d_in[12];
    const float* conv_b2  = (const float*)d_in[13];
    const float* ln_g     = (const float*)d_in[14];
    const float* ln_b     = (const float*)d_in[15];
    const float* out_w1   = (const float*)d_in[16];
    const float* out_b1   = (const float*)d_in[17];
    const float* out_w2   = (const float*)d_in[18];
    const float* out_b2   = (const float*)d_in[19];
    const float* out_w3   = (const float*)d_in[20];
    const float* out_b3   = (const float*)d_in[21];
    float* out = (float*)d_out;

    float *x, *xw, *aggr, *cnt, *pool, *gcnt;
    __half *eh, *w1h, *w2h;
    cudaGetSymbolAddress((void**)&x,    g_x);
    cudaGetSymbolAddress((void**)&eh,   g_eh);
    cudaGetSymbolAddress((void**)&xw,   g_xw);
    cudaGetSymbolAddress((void**)&aggr, g_aggr);
    cudaGetSymbolAddress((void**)&cnt,  g_cnt);
    cudaGetSymbolAddress((void**)&pool, g_pool);
    cudaGetSymbolAddress((void**)&gcnt, g_gcnt);
    cudaGetSymbolAddress((void**)&w1h,  g_w1h);
    cudaGetSymbolAddress((void**)&w2h,  g_w2h);

    static int smem_set = 0;
    if (!smem_set) {
        cudaFuncSetAttribute(k_conv_fused,
                             cudaFuncAttributeMaxDynamicSharedMemorySize, SMEM_TOTAL);
        smem_set = 1;
    }

    cudaMemsetAsync(cnt,  0, N_NODES * sizeof(float), 0);
    cudaMemsetAsync(pool, 0, N_GRAPHS * HDIM * sizeof(float), 0);
    cudaMemsetAsync(gcnt, 0, N_GRAPHS * sizeof(float), 0);

    k_node_embed<<<N_NODES, 128>>>(atom_fea, emb_w, emb_b, emb_ln_g, emb_ln_b, x);
    k_edge_embed<<<N_EDGES / 64, 128>>>(nbr_fea, edge_w, edge_b, eh);
    k_cnt<<<ceildiv(N_EDGES, 256), 256>>>(nbr_idx, cnt, N_EDGES);

    for (int i = 0; i < NLAYERS; i++) {
        const float* W1a = conv_w1 + (long)i * 256 * 256;   // rows 0..127
        const float* W1b = W1a + 128 * 256;                  // rows 128..255
        const float* W2  = conv_w2 + (long)i * 256 * 128;
        const float* b1  = conv_b1 + (long)i * 256;
        const float* b2  = conv_b2 + (long)i * 128;

        k_cvt<<<64, 512>>>(W1b, W2, w1h, w2h);
        // XW = x @ W1a + b1   [50000, 256] fp32
        sgemm_bias<<<dim3(2, ceildiv(N_NODES, 128)), 256>>>(
            x, W1a, xw, N_NODES, 256, 128, b1);
        cudaMemsetAsync(aggr, 0, N_NODES * HDIM * sizeof(float), 0);
        // fused: M1 = silu(e@W1b + XW[src]); aggr[dst] += silu(M1@W2 + b2)
        k_conv_fused<<<N_EDGES / 128, 256, SMEM_TOTAL>>>(
            eh, w1h, w2h, xw, b2, nbr_idx, aggr);
        // x = LN(x + aggr/cnt)
        k_ln_aggr<<<N_NODES, 128>>>(x, aggr, cnt, ln_g + i * 128, ln_b + i * 128);
    }

    k_pool<<<N_NODES, 128>>>(x, batch, pool, gcnt);
    k_head<<<N_GRAPHS, 128>>>(pool, gcnt, out_w1, out_b1, out_w2, out_b2,
                              out_w3, out_b3, out);
    (void)in_sizes; (void)n_in; (void)out_size;
}

// round 4
// speedup vs baseline: 3.3460x; 1.0719x over previous
#include <cuda_runtime.h>
#include <cuda_fp16.h>
#include <cstdint>

#define N_NODES 50000
#define N_EDGES 800000
#define N_GRAPHS 1024
#define NLAYERS 5
#define NT_TILES (N_EDGES / 128)   // 6250

// ---------------- scratch (device globals; no allocation allowed) ----------------
__device__ __align__(16) float  g_x[N_NODES * 128];
__device__ __align__(16) __half g_xh[N_NODES * 128];
__device__ __align__(16) __half g_eh[N_EDGES * 128];
__device__ __align__(16) float  g_xw[N_NODES * 256];
__device__ __align__(16) float  g_aggr[N_NODES * 128];
__device__ __align__(16) float  g_cnt[N_NODES];
__device__ __align__(16) float  g_pool[N_GRAPHS * 128];
__device__ __align__(16) float  g_gcnt[N_GRAPHS];

__device__ __forceinline__ float silu_f(float v) { return v / (1.0f + __expf(-v)); }

__device__ __forceinline__ uint32_t sptr(const void* p) {
    return (uint32_t)__cvta_generic_to_shared(p);
}
// XOR-swizzled byte offset: row-major tile, rowBytes per row, 16B chunk index c8
__device__ __forceinline__ uint32_t swz(int row, int c8, int rowBytes) {
    return (uint32_t)(row * rowBytes + (((c8 ^ (row & 7)) << 4)));
}
__device__ __forceinline__ void ldsm_x4(uint32_t* r, uint32_t addr) {
    asm volatile("ldmatrix.sync.aligned.m8n8.x4.shared.b16 {%0,%1,%2,%3}, [%4];\n"
                 : "=r"(r[0]), "=r"(r[1]), "=r"(r[2]), "=r"(r[3]) : "r"(addr));
}
__device__ __forceinline__ void ldsm_x4_t(uint32_t* r, uint32_t addr) {
    asm volatile("ldmatrix.sync.aligned.m8n8.x4.trans.shared.b16 {%0,%1,%2,%3}, [%4];\n"
                 : "=r"(r[0]), "=r"(r[1]), "=r"(r[2]), "=r"(r[3]) : "r"(addr));
}
__device__ __forceinline__ void mma_16816(float* c, const uint32_t* a, const uint32_t* b) {
    asm volatile(
        "mma.sync.aligned.m16n8k16.row.col.f32.f16.f16.f32 "
        "{%0,%1,%2,%3}, {%4,%5,%6,%7}, {%8,%9}, {%0,%1,%2,%3};\n"
        : "+f"(c[0]), "+f"(c[1]), "+f"(c[2]), "+f"(c[3])
        : "r"(a[0]), "r"(a[1]), "r"(a[2]), "r"(a[3]), "r"(b[0]), "r"(b[1]));
}
__device__ __forceinline__ void red2(float* p, float a, float b) {
    asm volatile("red.global.add.v2.f32 [%0], {%1,%2};" :: "l"(p), "f"(a), "f"(b) : "memory");
}

// block = 128 threads (4 warps). mean/var over the block.
__device__ __forceinline__ void ln_stats128(float v, float& mean, float& var,
                                            float* s1, float* s2) {
    float a = v, b = v * v;
    #pragma unroll
    for (int o = 16; o > 0; o >>= 1) {
        a += __shfl_down_sync(0xffffffffu, a, o);
        b += __shfl_down_sync(0xffffffffu, b, o);
    }
    int w = threadIdx.x >> 5;
    if ((threadIdx.x & 31) == 0) { s1[w] = a; s2[w] = b; }
    __syncthreads();
    if (threadIdx.x == 0) {
        s1[0] = s1[0] + s1[1] + s1[2] + s1[3];
        s2[0] = s2[0] + s2[1] + s2[2] + s2[3];
    }
    __syncthreads();
    mean = s1[0] * (1.0f / 128.0f);
    var  = s2[0] * (1.0f / 128.0f) - mean * mean;
}

// ---------------- node embedding ----------------
__global__ __launch_bounds__(128) void k_node_embed(
    const float* __restrict__ atom, const float* __restrict__ w,
    const float* __restrict__ b, const float* __restrict__ lg,
    const float* __restrict__ lb, float* __restrict__ x, __half* __restrict__ xh)
{
    __shared__ float s1[4], s2[4], sa[4];
    int n = blockIdx.x, h = threadIdx.x;
    if (h < 4) sa[h] = atom[n * 4 + h];
    __syncthreads();
    float v = b[h];
    #pragma unroll
    for (int k = 0; k < 4; k++) v = fmaf(sa[k], __ldg(&w[k * 128 + h]), v);
    float mean, var;
    ln_stats128(v, mean, var, s1, s2);
    float y = (v - mean) * rsqrtf(var + 1e-5f) * lg[h] + lb[h];
    float o = silu_f(y);
    x[n * 128 + h] = o;
    xh[n * 128 + h] = __float2half_rn(o);
}

// ---------------- edge embedding (vectorized) ----------------
__global__ __launch_bounds__(128) void k_edge_embed(
    const float* __restrict__ nbr, const float* __restrict__ w,
    const float* __restrict__ b, __half* __restrict__ e)
{
    __shared__ float snbr[64][44];
    const int h = threadIdx.x;
    const long e0 = (long)blockIdx.x * 64;
    float wr[44];
    #pragma unroll
    for (int k = 0; k < 41; k++) wr[k] = w[k * 128 + h];
    wr[41] = wr[42] = wr[43] = 0.0f;
    if (h < 64) { snbr[h][41] = 0.0f; snbr[h][42] = 0.0f; snbr[h][43] = 0.0f; }
    const float* base = nbr + e0 * 41;
    for (int t = h; t < 64 * 41; t += 128) snbr[t / 41][t % 41] = base[t];
    float bb = b[h];
    __syncthreads();
    #pragma unroll 2
    for (int r = 0; r < 64; r++) {
        float acc = bb;
        #pragma unroll
        for (int k4 = 0; k4 < 11; k4++) {
            float4 s = *(const float4*)&snbr[r][k4 * 4];
            acc = fmaf(s.x, wr[k4 * 4 + 0], acc);
            acc = fmaf(s.y, wr[k4 * 4 + 1], acc);
            acc = fmaf(s.z, wr[k4 * 4 + 2], acc);
            acc = fmaf(s.w, wr[k4 * 4 + 3], acc);
        }
        e[(e0 + r) * 128 + h] = __float2half_rn(silu_f(acc));
    }
}

// ---------------- degree count ----------------
__global__ void k_cnt(const int* __restrict__ idx, float* __restrict__ cnt, int nE) {
    int i = blockIdx.x * blockDim.x + threadIdx.x;
    if (i < nE) atomicAdd(&cnt[idx[2 * i + 1]], 1.0f);
}

// ================= HMMA kernels =================
// smem layouts (bytes)
#define CV_SE  0
#define CV_SW1 32768
#define CV_SW2 98304
#define CV_SM1 163840
#define CV_SMEM 229376

#define XW_SE 0
#define XW_SW 32768
#define XW_SMEM 98304

// load fp32 weight [KR x NC] row-major -> swizzled fp16 smem tile (rowBytes = NC*2)
template <int KR, int NC>
__device__ __forceinline__ void wload(char* sdst, const float* __restrict__ W, int tid) {
    const float4* wv = (const float4*)W;
    constexpr int NV = NC / 4;
    #pragma unroll 4
    for (int i = tid; i < KR * NV; i += 512) {
        int k = i / NV, n4 = (i % NV) * 4;
        float4 v = __ldg(&wv[i]);
        __half2 a = __floats2half2_rn(v.x, v.y);
        __half2 b = __floats2half2_rn(v.z, v.w);
        char* p = sdst + swz(k, n4 >> 3, NC * 2) + ((n4 & 7) << 1);
        *(uint32_t*)p = *(uint32_t*)&a;
        *(uint32_t*)(p + 4) = *(uint32_t*)&b;
    }
}

// ---------------- XW = x @ W1a + b1 (HMMA, one tile of 128 rows per block) ----------------
__global__ __launch_bounds__(512) void k_xw(
    const __half* __restrict__ Xh, const float* __restrict__ W1a,
    const float* __restrict__ b1, float* __restrict__ XW)
{
    extern __shared__ char sm[];
    const int tid = threadIdx.x, lane = tid & 31, warp = tid >> 5;
    const int wm = (warp & 3) * 32, wn = warp >> 2;   // warp tile 32x64 over 128x256
    const int g = lane >> 2, t = lane & 3;
    const uint32_t sbase = sptr(sm);
    const long rowBase = (long)blockIdx.x * 128;

    wload<128, 256>(sm + XW_SW, W1a, tid);
    // A tile (clamped rows)
    {
        int row = tid >> 2, cb = (tid & 3) * 4;
        long grow = rowBase + row;
        if (grow >= N_NODES) grow = N_NODES - 1;
        const uint4* p = (const uint4*)(Xh + grow * 128) + cb;
        #pragma unroll
        for (int j = 0; j < 4; j++)
            *(uint4*)(sm + XW_SE + swz(row, cb + j, 256)) = __ldg(p + j);
    }
    __syncthreads();

    float acc[2][8][4];
    #pragma unroll
    for (int mi = 0; mi < 2; mi++)
        #pragma unroll
        for (int nj = 0; nj < 8; nj++)
            #pragma unroll
            for (int q = 0; q < 4; q++) acc[mi][nj][q] = 0.0f;

    for (int ks = 0; ks < 8; ks++) {
        uint32_t af[2][4], bf[8][2];
        #pragma unroll
        for (int mi = 0; mi < 2; mi++)
            ldsm_x4(af[mi], sbase + XW_SE +
                    swz(wm + mi * 16 + (lane & 15), ks * 2 + (lane >> 4), 256));
        #pragma unroll
        for (int np = 0; np < 4; np++) {
            uint32_t r4[4];
            ldsm_x4_t(r4, sbase + XW_SW +
                      swz(ks * 16 + (lane & 15), wn * 8 + np * 2 + (lane >> 4), 512));
            bf[np * 2 + 0][0] = r4[0]; bf[np * 2 + 0][1] = r4[1];
            bf[np * 2 + 1][0] = r4[2]; bf[np * 2 + 1][1] = r4[3];
        }
        #pragma unroll
        for (int mi = 0; mi < 2; mi++)
            #pragma unroll
            for (int nj = 0; nj < 8; nj++)
                mma_16816(acc[mi][nj], af[mi], bf[nj]);
    }

    #pragma unroll
    for (int mi = 0; mi < 2; mi++) {
        long g0 = rowBase + wm + mi * 16 + g, g1 = g0 + 8;
        #pragma unroll
        for (int nj = 0; nj < 8; nj++) {
            int col = wn * 64 + nj * 8 + 2 * t;
            float2 bb = *(const float2*)(b1 + col);
            if (g0 < N_NODES) {
                float2 o = make_float2(acc[mi][nj][0] + bb.x, acc[mi][nj][1] + bb.y);
                *(float2*)(XW + g0 * 256 + col) = o;
            }
            if (g1 < N_NODES) {
                float2 o = make_float2(acc[mi][nj][2] + bb.x, acc[mi][nj][3] + bb.y);
                *(float2*)(XW + g1 * 256 + col) = o;
            }
        }
    }
}

// ---------------- fused conv layer (persistent, weights resident) ----------------
__global__ __launch_bounds__(512) void k_conv(
    const __half* __restrict__ E, const float* __restrict__ W1b,
    const float* __restrict__ W2, const float* __restrict__ XW,
    const float* __restrict__ b2, const int2* __restrict__ idx,
    float* __restrict__ aggr)
{
    extern __shared__ char sm[];
    const int tid = threadIdx.x, lane = tid & 31, warp = tid >> 5;
    const int wm = (warp & 3) * 32, wn = warp >> 2;
    const int g = lane >> 2, t = lane & 3;
    const uint32_t sbase = sptr(sm);

    wload<128, 256>(sm + CV_SW1, W1b, tid);
    wload<256, 128>(sm + CV_SW2, W2, tid);

    const int erow = tid >> 2, ecb = (tid & 3) * 4;
    uint4 er[4];
    long tile = blockIdx.x;
    if (tile < NT_TILES) {
        const uint4* p = (const uint4*)(E + (tile * 128 + erow) * 128) + ecb;
        #pragma unroll
        for (int j = 0; j < 4; j++) er[j] = __ldg(p + j);
    }

    while (tile < NT_TILES) {
        #pragma unroll
        for (int j = 0; j < 4; j++)
            *(uint4*)(sm + CV_SE + swz(erow, ecb + j, 256)) = er[j];
        __syncthreads();
        long nxt = tile + gridDim.x;
        if (nxt < NT_TILES) {
            const uint4* p = (const uint4*)(E + (nxt * 128 + erow) * 128) + ecb;
            #pragma unroll
            for (int j = 0; j < 4; j++) er[j] = __ldg(p + j);
        }
        const long ebase = tile * 128;

        // ---- phase 1: D1 = E @ W1b  (128x256, K=128) ----
        float acc[2][8][4];
        #pragma unroll
        for (int mi = 0; mi < 2; mi++)
            #pragma unroll
            for (int nj = 0; nj < 8; nj++)
                #pragma unroll
                for (int q = 0; q < 4; q++) acc[mi][nj][q] = 0.0f;

        for (int ks = 0; ks < 8; ks++) {
            uint32_t af[2][4], bf[8][2];
            #pragma unroll
            for (int mi = 0; mi < 2; mi++)
                ldsm_x4(af[mi], sbase + CV_SE +
                        swz(wm + mi * 16 + (lane & 15), ks * 2 + (lane >> 4), 256));
            #pragma unroll
            for (int np = 0; np < 4; np++) {
                uint32_t r4[4];
                ldsm_x4_t(r4, sbase + CV_SW1 +
                          swz(ks * 16 + (lane & 15), wn * 8 + np * 2 + (lane >> 4), 512));
                bf[np * 2 + 0][0] = r4[0]; bf[np * 2 + 0][1] = r4[1];
                bf[np * 2 + 1][0] = r4[2]; bf[np * 2 + 1][1] = r4[3];
            }
            #pragma unroll
            for (int mi = 0; mi < 2; mi++)
                #pragma unroll
                for (int nj = 0; nj < 8; nj++)
                    mma_16816(acc[mi][nj], af[mi], bf[nj]);
        }

        // ---- epilogue 1: M1 = silu(D1 + XW[src]) -> smem fp16 ----
        #pragma unroll
        for (int mi = 0; mi < 2; mi++) {
            int r0 = wm + mi * 16 + g, r1 = r0 + 8;
            int s0 = __ldg(&idx[ebase + r0].x);
            int s1 = __ldg(&idx[ebase + r1].x);
            const float* x0 = XW + (long)s0 * 256;
            const float* x1 = XW + (long)s1 * 256;
            #pragma unroll
            for (int nj = 0; nj < 8; nj++) {
                int col = wn * 64 + nj * 8 + 2 * t;
                float2 a0 = __ldg((const float2*)(x0 + col));
                float2 a1 = __ldg((const float2*)(x1 + col));
                __half2 h0 = __floats2half2_rn(silu_f(acc[mi][nj][0] + a0.x),
                                               silu_f(acc[mi][nj][1] + a0.y));
                __half2 h1 = __floats2half2_rn(silu_f(acc[mi][nj][2] + a1.x),
                                               silu_f(acc[mi][nj][3] + a1.y));
                *(uint32_t*)(sm + CV_SM1 + swz(r0, col >> 3, 512) + ((col & 7) << 1)) =
                    *(uint32_t*)&h0;
                *(uint32_t*)(sm + CV_SM1 + swz(r1, col >> 3, 512) + ((col & 7) << 1)) =
                    *(uint32_t*)&h1;
            }
        }
        __syncthreads();

        // ---- phase 2: D2 = M1 @ W2  (128x128, K=256) ----
        float ac2[2][4][4];
        #pragma unroll
        for (int mi = 0; mi < 2; mi++)
            #pragma unroll
            for (int nj = 0; nj < 4; nj++)
                #pragma unroll
                for (int q = 0; q < 4; q++) ac2[mi][nj][q] = 0.0f;

        for (int ks = 0; ks < 16; ks++) {
            uint32_t af[2][4], bf[4][2];
            #pragma unroll
            for (int mi = 0; mi < 2; mi++)
                ldsm_x4(af[mi], sbase + CV_SM1 +
                        swz(wm + mi * 16 + (lane & 15), ks * 2 + (lane >> 4), 512));
            #pragma unroll
            for (int np = 0; np < 2; np++) {
                uint32_t r4[4];
                ldsm_x4_t(r4, sbase + CV_SW2 +
                          swz(ks * 16 + (lane & 15), wn * 4 + np * 2 + (lane >> 4), 256));
                bf[np * 2 + 0][0] = r4[0]; bf[np * 2 + 0][1] = r4[1];
                bf[np * 2 + 1][0] = r4[2]; bf[np * 2 + 1][1] = r4[3];
            }
            #pragma unroll
            for (int mi = 0; mi < 2; mi++)
                #pragma unroll
                for (int nj = 0; nj < 4; nj++)
                    mma_16816(ac2[mi][nj], af[mi], bf[nj]);
        }

        // ---- epilogue 2: aggr[dst] += silu(D2 + b2)  (vector reds) ----
        #pragma unroll
        for (int mi = 0; mi < 2; mi++) {
            int r0 = wm + mi * 16 + g, r1 = r0 + 8;
            long d0 = __ldg(&idx[ebase + r0].y);
            long d1 = __ldg(&idx[ebase + r1].y);
            float* p0 = aggr + d0 * 128;
            float* p1 = aggr + d1 * 128;
            #pragma unroll
            for (int nj = 0; nj < 4; nj++) {
                int col = wn * 32 + nj * 8 + 2 * t;
                float2 bb = __ldg((const float2*)(b2 + col));
                red2(p0 + col, silu_f(ac2[mi][nj][0] + bb.x),
                               silu_f(ac2[mi][nj][1] + bb.y));
                red2(p1 + col, silu_f(ac2[mi][nj][2] + bb.x),
                               silu_f(ac2[mi][nj][3] + bb.y));
            }
        }
        __syncthreads();
        tile = nxt;
    }
}

// ---------------- x = LN(x + aggr/cnt) ; also emit fp16 ----------------
__global__ __launch_bounds__(128) void k_ln_aggr(
    float* __restrict__ x, __half* __restrict__ xh, const float* __restrict__ aggr,
    const float* __restrict__ cnt, const float* __restrict__ lg,
    const float* __restrict__ lb)
{
    __shared__ float s1[4], s2[4];
    int n = blockIdx.x, h = threadIdx.x;
    float c = cnt[n]; if (c < 1.0f) c = 1.0f;
    float t = x[n * 128 + h] + aggr[n * 128 + h] / c;
    float mean, var;
    ln_stats128(t, mean, var, s1, s2);
    float o = (t - mean) * rsqrtf(var + 1e-5f) * lg[h] + lb[h];
    x[n * 128 + h] = o;
    xh[n * 128 + h] = __float2half_rn(o);
}

// ---------------- graph pooling ----------------
__global__ __launch_bounds__(128) void k_pool(
    const float* __restrict__ x, const int* __restrict__ bm,
    float* __restrict__ pool, float* __restrict__ gcnt)
{
    int n = blockIdx.x, h = threadIdx.x;
    int g = bm[n];
    atomicAdd(&pool[g * 128 + h], x[n * 128 + h]);
    if (h == 0) atomicAdd(&gcnt[g], 1.0f);
}

// ---------------- output MLP ----------------
__global__ __launch_bounds__(128) void k_head(
    const float* __restrict__ pool, const float* __restrict__ gcnt,
    const float* __restrict__ w1, const float* __restrict__ b1,
    const float* __restrict__ w2, const float* __restrict__ b2,
    const float* __restrict__ w3, const float* __restrict__ b3,
    float* __restrict__ out)
{
    __shared__ float c[128], h1[128], h2[64];
    int g = blockIdx.x, h = threadIdx.x;
    float gc = gcnt[g]; if (gc < 1.0f) gc = 1.0f;
    c[h] = pool[g * 128 + h] / gc;
    __syncthreads();
    float a = b1[h];
    #pragma unroll 8
    for (int k = 0; k < 128; k++) a = fmaf(c[k], __ldg(&w1[k * 128 + h]), a);
    h1[h] = silu_f(a);
    __syncthreads();
    if (h < 64) {
        float a2 = b2[h];
        #pragma unroll 8
        for (int k = 0; k < 128; k++) a2 = fmaf(h1[k], __ldg(&w2[k * 64 + h]), a2);
        h2[h] = silu_f(a2);
    }
    __syncthreads();
    if (h < 3) {
        float a3 = b3[h];
        #pragma unroll
        for (int k = 0; k < 64; k++) a3 = fmaf(h2[k], __ldg(&w3[k * 3 + h]), a3);
        out[g * 3 + h] = a3;
    }
}

static inline int ceildiv(int a, int b) { return (a + b - 1) / b; }

extern "C" void kernel_launch(void* const* d_in, const int* in_sizes, int n_in,
                              void* d_out, int out_size)
{
    const float* atom_fea = (const float*)d_in[0];
    const float* nbr_fea  = (const float*)d_in[1];
    const int*   nbr_idx  = (const int*)  d_in[2];
    const int*   batch    = (const int*)  d_in[3];
    const float* emb_w    = (const float*)d_in[4];
    const float* emb_b    = (const float*)d_in[5];
    const float* emb_ln_g = (const float*)d_in[6];
    const float* emb_ln_b = (const float*)d_in[7];
    const float* edge_w   = (const float*)d_in[8];
    const float* edge_b   = (const float*)d_in[9];
    const float* conv_w1  = (const float*)d_in[10];
    const float* conv_b1  = (const float*)d_in[11];
    const float* conv_w2  = (const float*)d_in[12];
    const float* conv_b2  = (const float*)d_in[13];
    const float* ln_g     = (const float*)d_in[14];
    const float* ln_b     = (const float*)d_in[15];
    const float* out_w1   = (const float*)d_in[16];
    const float* out_b1   = (const float*)d_in[17];
    const float* out_w2   = (const float*)d_in[18];
    const float* out_b2   = (const float*)d_in[19];
    const float* out_w3   = (const float*)d_in[20];
    const float* out_b3   = (const float*)d_in[21];
    float* out = (float*)d_out;

    float *x, *xw, *aggr, *cnt, *pool, *gcnt;
    __half *xh, *eh;
    cudaGetSymbolAddress((void**)&x,    g_x);
    cudaGetSymbolAddress((void**)&xh,   g_xh);
    cudaGetSymbolAddress((void**)&eh,   g_eh);
    cudaGetSymbolAddress((void**)&xw,   g_xw);
    cudaGetSymbolAddress((void**)&aggr, g_aggr);
    cudaGetSymbolAddress((void**)&cnt,  g_cnt);
    cudaGetSymbolAddress((void**)&pool, g_pool);
    cudaGetSymbolAddress((void**)&gcnt, g_gcnt);

    static int attr_set = 0;
    if (!attr_set) {
        cudaFuncSetAttribute(k_conv,
                             cudaFuncAttributeMaxDynamicSharedMemorySize, CV_SMEM);
        cudaFuncSetAttribute(k_xw,
                             cudaFuncAttributeMaxDynamicSharedMemorySize, XW_SMEM);
        attr_set = 1;
    }

    cudaMemsetAsync(cnt,  0, N_NODES * sizeof(float), 0);
    cudaMemsetAsync(pool, 0, N_GRAPHS * 128 * sizeof(float), 0);
    cudaMemsetAsync(gcnt, 0, N_GRAPHS * sizeof(float), 0);

    k_node_embed<<<N_NODES, 128>>>(atom_fea, emb_w, emb_b, emb_ln_g, emb_ln_b, x, xh);
    k_edge_embed<<<N_EDGES / 64, 128>>>(nbr_fea, edge_w, edge_b, eh);
    k_cnt<<<ceildiv(N_EDGES, 256), 256>>>(nbr_idx, cnt, N_EDGES);

    for (int i = 0; i < NLAYERS; i++) {
        const float* W1a = conv_w1 + (long)i * 256 * 256;   // rows 0..127
        const float* W1b = W1a + 128 * 256;                  // rows 128..255
        const float* W2  = conv_w2 + (long)i * 256 * 128;
        const float* b1  = conv_b1 + (long)i * 256;
        const float* b2  = conv_b2 + (long)i * 128;

        k_xw<<<ceildiv(N_NODES, 128), 512, XW_SMEM>>>(xh, W1a, b1, xw);
        cudaMemsetAsync(aggr, 0, N_NODES * 128 * sizeof(float), 0);
        k_conv<<<152, 512, CV_SMEM>>>(eh, W1b, W2, xw, b2,
                                      (const int2*)nbr_idx, aggr);
        k_ln_aggr<<<N_NODES, 128>>>(x, xh, aggr, cnt, ln_g + i * 128, ln_b + i * 128);
    }

    k_pool<<<N_NODES, 128>>>(x, batch, pool, gcnt);
    k_head<<<N_GRAPHS, 128>>>(pool, gcnt, out_w1, out_b1, out_w2, out_b2,
                              out_w3, out_b3, out);
    (void)in_sizes; (void)n_in; (void)out_size;
}

// round 5
// speedup vs baseline: 3.9452x; 1.1791x over previous
#include <cuda_runtime.h>
#include <cuda_fp16.h>
#include <cstdint>

#define N_NODES 50000
#define N_EDGES 800000
#define N_GRAPHS 1024
#define NLAYERS 5
#define NT_TILES (N_EDGES / 128)   // 6250

// ---------------- scratch (device globals; no allocation allowed) ----------------
__device__ __align__(16) float  g_x[N_NODES * 128];
__device__ __align__(16) __half g_xh[N_NODES * 128];
__device__ __align__(16) __half g_eh[N_EDGES * 128];     // dst-sorted edge features
__device__ __align__(16) __half g_xw[N_NODES * 256];     // fp16 XW = x@W1a + b1
__device__ __align__(16) float  g_aggr[N_NODES * 128];
__device__ __align__(16) float  g_pool[N_GRAPHS * 128];
__device__ __align__(16) float  g_gcnt[N_GRAPHS];
__device__ int g_deg[N_NODES];
__device__ int g_cur[N_NODES];
__device__ int g_off[N_NODES];
__device__ int g_pos[N_EDGES];
__device__ int g_srcs[N_EDGES];
__device__ int g_dsts[N_EDGES];

__device__ __forceinline__ float silu_f(float v) { return v / (1.0f + __expf(-v)); }

__device__ __forceinline__ uint32_t sptr(const void* p) {
    return (uint32_t)__cvta_generic_to_shared(p);
}
__device__ __forceinline__ uint32_t swz(int row, int c8, int rowBytes) {
    return (uint32_t)(row * rowBytes + (((c8 ^ (row & 7)) << 4)));
}
__device__ __forceinline__ void ldsm_x4(uint32_t* r, uint32_t addr) {
    asm volatile("ldmatrix.sync.aligned.m8n8.x4.shared.b16 {%0,%1,%2,%3}, [%4];\n"
                 : "=r"(r[0]), "=r"(r[1]), "=r"(r[2]), "=r"(r[3]) : "r"(addr));
}
__device__ __forceinline__ void ldsm_x4_t(uint32_t* r, uint32_t addr) {
    asm volatile("ldmatrix.sync.aligned.m8n8.x4.trans.shared.b16 {%0,%1,%2,%3}, [%4];\n"
                 : "=r"(r[0]), "=r"(r[1]), "=r"(r[2]), "=r"(r[3]) : "r"(addr));
}
__device__ __forceinline__ void mma_16816(float* c, const uint32_t* a, const uint32_t* b) {
    asm volatile(
        "mma.sync.aligned.m16n8k16.row.col.f32.f16.f16.f32 "
        "{%0,%1,%2,%3}, {%4,%5,%6,%7}, {%8,%9}, {%0,%1,%2,%3};\n"
        : "+f"(c[0]), "+f"(c[1]), "+f"(c[2]), "+f"(c[3])
        : "r"(a[0]), "r"(a[1]), "r"(a[2]), "r"(a[3]), "r"(b[0]), "r"(b[1]));
}
__device__ __forceinline__ void red2(float* p, float a, float b) {
    asm volatile("red.global.add.v2.f32 [%0], {%1,%2};" :: "l"(p), "f"(a), "f"(b) : "memory");
}
#define CP_ASYNC16(sdst, gsrc) \
    asm volatile("cp.async.ca.shared.global [%0], [%1], 16;" :: "r"(sdst), "l"(gsrc) : "memory")
#define CP_COMMIT() asm volatile("cp.async.commit_group;" ::: "memory")
#define CP_WAIT0()  asm volatile("cp.async.wait_group 0;" ::: "memory")

// block = 128 threads (4 warps). mean/var over the block.
__device__ __forceinline__ void ln_stats128(float v, float& mean, float& var,
                                            float* s1, float* s2) {
    float a = v, b = v * v;
    #pragma unroll
    for (int o = 16; o > 0; o >>= 1) {
        a += __shfl_down_sync(0xffffffffu, a, o);
        b += __shfl_down_sync(0xffffffffu, b, o);
    }
    int w = threadIdx.x >> 5;
    if ((threadIdx.x & 31) == 0) { s1[w] = a; s2[w] = b; }
    __syncthreads();
    if (threadIdx.x == 0) {
        s1[0] = s1[0] + s1[1] + s1[2] + s1[3];
        s2[0] = s2[0] + s2[1] + s2[2] + s2[3];
    }
    __syncthreads();
    mean = s1[0] * (1.0f / 128.0f);
    var  = s2[0] * (1.0f / 128.0f) - mean * mean;
}

// ---------------- node embedding ----------------
__global__ __launch_bounds__(128) void k_node_embed(
    const float* __restrict__ atom, const float* __restrict__ w,
    const float* __restrict__ b, const float* __restrict__ lg,
    const float* __restrict__ lb, float* __restrict__ x, __half* __restrict__ xh)
{
    __shared__ float s1[4], s2[4], sa[4];
    int n = blockIdx.x, h = threadIdx.x;
    if (h < 4) sa[h] = atom[n * 4 + h];
    __syncthreads();
    float v = b[h];
    #pragma unroll
    for (int k = 0; k < 4; k++) v = fmaf(sa[k], __ldg(&w[k * 128 + h]), v);
    float mean, var;
    ln_stats128(v, mean, var, s1, s2);
    float y = (v - mean) * rsqrtf(var + 1e-5f) * lg[h] + lb[h];
    float o = silu_f(y);
    x[n * 128 + h] = o;
    xh[n * 128 + h] = __float2half_rn(o);
}

// ---------------- degree count (int) ----------------
__global__ void k_deg(const int* __restrict__ idx, int* __restrict__ deg, int nE) {
    int i = blockIdx.x * blockDim.x + threadIdx.x;
    if (i < nE) atomicAdd(&deg[idx[2 * i + 1]], 1);
}

// ---------------- exclusive prefix scan over deg (one block) ----------------
#define SCAN_CH 49
__global__ __launch_bounds__(1024) void k_scan(const int* __restrict__ deg,
                                               int* __restrict__ off)
{
    __shared__ int wsum[32];
    int tid = threadIdx.x, lane = tid & 31, w = tid >> 5;
    int base = tid * SCAN_CH;
    int s = 0;
    for (int j = 0; j < SCAN_CH; j++) {
        int ix = base + j;
        if (ix < N_NODES) s += deg[ix];
    }
    int incl = s;
    #pragma unroll
    for (int o = 1; o < 32; o <<= 1) {
        int t2 = __shfl_up_sync(0xffffffffu, incl, o);
        if (lane >= o) incl += t2;
    }
    if (lane == 31) wsum[w] = incl;
    __syncthreads();
    if (w == 0) {
        int v = wsum[lane];
        #pragma unroll
        for (int o = 1; o < 32; o <<= 1) {
            int t2 = __shfl_up_sync(0xffffffffu, v, o);
            if (lane >= o) v += t2;
        }
        wsum[lane] = v;
    }
    __syncthreads();
    int run = incl - s + (w > 0 ? wsum[w - 1] : 0);
    for (int j = 0; j < SCAN_CH; j++) {
        int ix = base + j;
        if (ix < N_NODES) { off[ix] = run; run += deg[ix]; }
    }
}

// ---------------- edge scatter (counting sort by dst) ----------------
__global__ void k_scatter(const int* __restrict__ nbr, const int* __restrict__ off,
                          int* __restrict__ cur, int* __restrict__ pos,
                          int* __restrict__ srcs, int* __restrict__ dsts)
{
    int i = blockIdx.x * blockDim.x + threadIdx.x;
    if (i < N_EDGES) {
        int d = nbr[2 * i + 1];
        int p = off[d] + atomicAdd(&cur[d], 1);
        pos[i] = p;
        srcs[p] = nbr[2 * i];
        dsts[p] = d;
    }
}

// ---------------- edge embedding (vectorized, writes permuted rows) ----------------
__global__ __launch_bounds__(128) void k_edge_embed(
    const float* __restrict__ nbr, const float* __restrict__ w,
    const float* __restrict__ b, const int* __restrict__ pos, __half* __restrict__ e)
{
    __shared__ float snbr[64][44];
    __shared__ int spos[64];
    const int h = threadIdx.x;
    const long e0 = (long)blockIdx.x * 64;
    float wr[44];
    #pragma unroll
    for (int k = 0; k < 41; k++) wr[k] = w[k * 128 + h];
    wr[41] = wr[42] = wr[43] = 0.0f;
    if (h < 64) {
        snbr[h][41] = 0.0f; snbr[h][42] = 0.0f; snbr[h][43] = 0.0f;
        spos[h] = pos[e0 + h];
    }
    const float* base = nbr + e0 * 41;
    for (int t = h; t < 64 * 41; t += 128) snbr[t / 41][t % 41] = base[t];
    float bb = b[h];
    __syncthreads();
    #pragma unroll 2
    for (int r = 0; r < 64; r++) {
        float acc = bb;
        #pragma unroll
        for (int k4 = 0; k4 < 11; k4++) {
            float4 s = *(const float4*)&snbr[r][k4 * 4];
            acc = fmaf(s.x, wr[k4 * 4 + 0], acc);
            acc = fmaf(s.y, wr[k4 * 4 + 1], acc);
            acc = fmaf(s.z, wr[k4 * 4 + 2], acc);
            acc = fmaf(s.w, wr[k4 * 4 + 3], acc);
        }
        e[(long)spos[r] * 128 + h] = __float2half_rn(silu_f(acc));
    }
}

// ================= HMMA kernels =================
#define CV_SE  0
#define CV_SW1 32768
#define CV_SW2 98304
#define CV_SM1 163840
#define CV_IDX 229376
#define CV_SMEM 230400

#define XW_SE 0
#define XW_SW 32768
#define XW_SMEM 98304

template <int KR, int NC>
__device__ __forceinline__ void wload(char* sdst, const float* __restrict__ W, int tid) {
    const float4* wv = (const float4*)W;
    constexpr int NV = NC / 4;
    #pragma unroll 4
    for (int i = tid; i < KR * NV; i += 512) {
        int k = i / NV, n4 = (i % NV) * 4;
        float4 v = __ldg(&wv[i]);
        __half2 a = __floats2half2_rn(v.x, v.y);
        __half2 b = __floats2half2_rn(v.z, v.w);
        char* p = sdst + swz(k, n4 >> 3, NC * 2) + ((n4 & 7) << 1);
        *(uint32_t*)p = *(uint32_t*)&a;
        *(uint32_t*)(p + 4) = *(uint32_t*)&b;
    }
}

// ---------------- XW = x @ W1a + b1 (HMMA, fp16 output) ----------------
__global__ __launch_bounds__(512) void k_xw(
    const __half* __restrict__ Xh, const float* __restrict__ W1a,
    const float* __restrict__ b1, __half* __restrict__ XW)
{
    extern __shared__ char sm[];
    const int tid = threadIdx.x, lane = tid & 31, warp = tid >> 5;
    const int wm = (warp & 3) * 32, wn = warp >> 2;
    const int g = lane >> 2, t = lane & 3;
    const uint32_t sbase = sptr(sm);
    const long rowBase = (long)blockIdx.x * 128;

    wload<128, 256>(sm + XW_SW, W1a, tid);
    {
        int row = tid >> 2, cb = (tid & 3) * 4;
        long grow = rowBase + row;
        if (grow >= N_NODES) grow = N_NODES - 1;
        const uint4* p = (const uint4*)(Xh + grow * 128) + cb;
        #pragma unroll
        for (int j = 0; j < 4; j++)
            *(uint4*)(sm + XW_SE + swz(row, cb + j, 256)) = __ldg(p + j);
    }
    __syncthreads();

    float acc[2][8][4];
    #pragma unroll
    for (int mi = 0; mi < 2; mi++)
        #pragma unroll
        for (int nj = 0; nj < 8; nj++)
            #pragma unroll
            for (int q = 0; q < 4; q++) acc[mi][nj][q] = 0.0f;

    for (int ks = 0; ks < 8; ks++) {
        uint32_t af[2][4], bf[8][2];
        #pragma unroll
        for (int mi = 0; mi < 2; mi++)
            ldsm_x4(af[mi], sbase + XW_SE +
                    swz(wm + mi * 16 + (lane & 15), ks * 2 + (lane >> 4), 256));
        #pragma unroll
        for (int np = 0; np < 4; np++) {
            uint32_t r4[4];
            ldsm_x4_t(r4, sbase + XW_SW +
                      swz(ks * 16 + (lane & 15), wn * 8 + np * 2 + (lane >> 4), 512));
            bf[np * 2 + 0][0] = r4[0]; bf[np * 2 + 0][1] = r4[1];
            bf[np * 2 + 1][0] = r4[2]; bf[np * 2 + 1][1] = r4[3];
        }
        #pragma unroll
        for (int mi = 0; mi < 2; mi++)
            #pragma unroll
            for (int nj = 0; nj < 8; nj++)
                mma_16816(acc[mi][nj], af[mi], bf[nj]);
    }

    #pragma unroll
    for (int mi = 0; mi < 2; mi++) {
        long g0 = rowBase + wm + mi * 16 + g, g1 = g0 + 8;
        #pragma unroll
        for (int nj = 0; nj < 8; nj++) {
            int col = wn * 64 + nj * 8 + 2 * t;
            float2 bb = *(const float2*)(b1 + col);
            if (g0 < N_NODES) {
                __half2 h = __floats2half2_rn(acc[mi][nj][0] + bb.x, acc[mi][nj][1] + bb.y);
                *(uint32_t*)(XW + g0 * 256 + col) = *(uint32_t*)&h;
            }
            if (g1 < N_NODES) {
                __half2 h = __floats2half2_rn(acc[mi][nj][2] + bb.x, acc[mi][nj][3] + bb.y);
                *(uint32_t*)(XW + g1 * 256 + col) = *(uint32_t*)&h;
            }
        }
    }
}

// ---------------- fused conv layer (persistent, sorted edges) ----------------
__global__ __launch_bounds__(512) void k_conv(
    const __half* __restrict__ E, const float* __restrict__ W1b,
    const float* __restrict__ W2, const __half* __restrict__ XW,
    const float* __restrict__ b2, const int* __restrict__ srcs,
    const int* __restrict__ dsts, float* __restrict__ aggr)
{
    extern __shared__ char sm[];
    const int tid = threadIdx.x, lane = tid & 31, warp = tid >> 5;
    const int wm = (warp & 3) * 32, wn = warp >> 2;
    const int g = lane >> 2, t = lane & 3;
    const uint32_t sbase = sptr(sm);
    int* sSrc = (int*)(sm + CV_IDX);
    int* sDst = sSrc + 128;

    wload<128, 256>(sm + CV_SW1, W1b, tid);
    wload<256, 128>(sm + CV_SW2, W2, tid);

    const int erow = tid >> 2, ecb = (tid & 3) * 4;
    uint4 er[4];
    int sv = 0, dv = 0;
    long tile = blockIdx.x;
    if (tile < NT_TILES) {
        const uint4* p = (const uint4*)(E + (tile * 128 + erow) * 128) + ecb;
        #pragma unroll
        for (int j = 0; j < 4; j++) er[j] = __ldg(p + j);
        if (tid < 128) {
            sv = __ldg(&srcs[tile * 128 + tid]);
            dv = __ldg(&dsts[tile * 128 + tid]);
        }
    }

    while (tile < NT_TILES) {
        #pragma unroll
        for (int j = 0; j < 4; j++)
            *(uint4*)(sm + CV_SE + swz(erow, ecb + j, 256)) = er[j];
        if (tid < 128) { sSrc[tid] = sv; sDst[tid] = dv; }
        __syncthreads();   // S1: E + idx visible

        // issue XW gather (fp16, 64KB per tile) into CV_SM1 via cp.async
        #pragma unroll
        for (int p = 0; p < 8; p++) {
            int i = tid + p * 512;
            int row = i >> 5, c8 = i & 31;
            uint32_t dstA = sbase + CV_SM1 + swz(row, c8, 512);
            const __half* srcA = XW + (long)sSrc[row] * 256 + c8 * 8;
            CP_ASYNC16(dstA, srcA);
        }
        CP_COMMIT();

        long nxt = tile + gridDim.x;
        if (nxt < NT_TILES) {
            const uint4* p = (const uint4*)(E + (nxt * 128 + erow) * 128) + ecb;
            #pragma unroll
            for (int j = 0; j < 4; j++) er[j] = __ldg(p + j);
            if (tid < 128) {
                sv = __ldg(&srcs[nxt * 128 + tid]);
                dv = __ldg(&dsts[nxt * 128 + tid]);
            }
        }

        // ---- phase 1: D1 = E @ W1b  (128x256, K=128) ----
        float acc[2][8][4];
        #pragma unroll
        for (int mi = 0; mi < 2; mi++)
            #pragma unroll
            for (int nj = 0; nj < 8; nj++)
                #pragma unroll
                for (int q = 0; q < 4; q++) acc[mi][nj][q] = 0.0f;

        for (int ks = 0; ks < 8; ks++) {
            uint32_t af[2][4], bf[8][2];
            #pragma unroll
            for (int mi = 0; mi < 2; mi++)
                ldsm_x4(af[mi], sbase + CV_SE +
                        swz(wm + mi * 16 + (lane & 15), ks * 2 + (lane >> 4), 256));
            #pragma unroll
            for (int np = 0; np < 4; np++) {
                uint32_t r4[4];
                ldsm_x4_t(r4, sbase + CV_SW1 +
                          swz(ks * 16 + (lane & 15), wn * 8 + np * 2 + (lane >> 4), 512));
                bf[np * 2 + 0][0] = r4[0]; bf[np * 2 + 0][1] = r4[1];
                bf[np * 2 + 1][0] = r4[2]; bf[np * 2 + 1][1] = r4[3];
            }
            #pragma unroll
            for (int mi = 0; mi < 2; mi++)
                #pragma unroll
                for (int nj = 0; nj < 8; nj++)
                    mma_16816(acc[mi][nj], af[mi], bf[nj]);
        }

        CP_WAIT0();
        __syncthreads();   // S2: gather staged, phase-1 E reads done

        // ---- epilogue 1: M1 = silu(D1 + XW_staged) in-place in CV_SM1 (fp16) ----
        #pragma unroll
        for (int mi = 0; mi < 2; mi++) {
            int r0 = wm + mi * 16 + g, r1 = r0 + 8;
            #pragma unroll
            for (int nj = 0; nj < 8; nj++) {
                int col = wn * 64 + nj * 8 + 2 * t;
                uint32_t a0o = CV_SM1 + swz(r0, col >> 3, 512) + ((col & 7) << 1);
                uint32_t a1o = CV_SM1 + swz(r1, col >> 3, 512) + ((col & 7) << 1);
                __half2 x0 = *(__half2*)(sm + a0o);
                __half2 x1 = *(__half2*)(sm + a1o);
                float2 f0 = __half22float2(x0), f1 = __half22float2(x1);
                __half2 h0 = __floats2half2_rn(silu_f(acc[mi][nj][0] + f0.x),
                                               silu_f(acc[mi][nj][1] + f0.y));
                __half2 h1 = __floats2half2_rn(silu_f(acc[mi][nj][2] + f1.x),
                                               silu_f(acc[mi][nj][3] + f1.y));
                *(__half2*)(sm + a0o) = h0;
                *(__half2*)(sm + a1o) = h1;
            }
        }
        __syncthreads();   // S3: M1 complete

        // ---- phase 2: D2 = M1 @ W2  (128x128, K=256) ----
        float ac2[2][4][4];
        #pragma unroll
        for (int mi = 0; mi < 2; mi++)
            #pragma unroll
            for (int nj = 0; nj < 4; nj++)
                #pragma unroll
                for (int q = 0; q < 4; q++) ac2[mi][nj][q] = 0.0f;

        for (int ks = 0; ks < 16; ks++) {
            uint32_t af[2][4], bf[4][2];
            #pragma unroll
            for (int mi = 0; mi < 2; mi++)
                ldsm_x4(af[mi], sbase + CV_SM1 +
                        swz(wm + mi * 16 + (lane & 15), ks * 2 + (lane >> 4), 512));
            #pragma unroll
            for (int np = 0; np < 2; np++) {
                uint32_t r4[4];
                ldsm_x4_t(r4, sbase + CV_SW2 +
                          swz(ks * 16 + (lane & 15), wn * 4 + np * 2 + (lane >> 4), 256));
                bf[np * 2 + 0][0] = r4[0]; bf[np * 2 + 0][1] = r4[1];
                bf[np * 2 + 1][0] = r4[2]; bf[np * 2 + 1][1] = r4[3];
            }
            #pragma unroll
            for (int mi = 0; mi < 2; mi++)
                #pragma unroll
                for (int nj = 0; nj < 4; nj++)
                    mma_16816(ac2[mi][nj], af[mi], bf[nj]);
        }

        // ---- epilogue 2a: stage silu(D2 + b2) fp16 into CV_SE (dead E region) ----
        #pragma unroll
        for (int mi = 0; mi < 2; mi++) {
            int r0 = wm + mi * 16 + g, r1 = r0 + 8;
            #pragma unroll
            for (int nj = 0; nj < 4; nj++) {
                int col = wn * 32 + nj * 8 + 2 * t;
                float2 bb = __ldg((const float2*)(b2 + col));
                __half2 h0 = __floats2half2_rn(silu_f(ac2[mi][nj][0] + bb.x),
                                               silu_f(ac2[mi][nj][1] + bb.y));
                __half2 h1 = __floats2half2_rn(silu_f(ac2[mi][nj][2] + bb.x),
                                               silu_f(ac2[mi][nj][3] + bb.y));
                *(__half2*)(sm + CV_SE + swz(r0, col >> 3, 256) + ((col & 7) << 1)) = h0;
                *(__half2*)(sm + CV_SE + swz(r1, col >> 3, 256) + ((col & 7) << 1)) = h1;
            }
        }
        __syncthreads();   // S4: staged D2 visible

        // ---- epilogue 2b: segmented reduction over dst-sorted rows ----
        {
            int cp2 = tid & 63;          // column pair: cols 2cp2, 2cp2+1
            int q = tid >> 6;            // row chunk: rows 16q..16q+15
            int col = 2 * cp2;
            float ax = 0.0f, ay = 0.0f;
            int prev = sDst[16 * q];
            #pragma unroll
            for (int r16 = 0; r16 < 16; r16++) {
                int r = 16 * q + r16;
                int d = sDst[r];
                if (d != prev) {
                    red2(aggr + (long)prev * 128 + col, ax, ay);
                    ax = 0.0f; ay = 0.0f; prev = d;
                }
                uint32_t hv = *(uint32_t*)(sm + CV_SE + swz(r, col >> 3, 256) +
                                           ((col & 7) << 1));
                float2 v = __half22float2(*(__half2*)&hv);
                ax += v.x; ay += v.y;
            }
            red2(aggr + (long)prev * 128 + col, ax, ay);
        }
        __syncthreads();   // S5: CV_SE / CV_SM1 free for next tile
        tile = nxt;
    }
}

// ---------------- x = LN(x + aggr/cnt), zero aggr, emit fp16 ----------------
__global__ __launch_bounds__(128) void k_ln_aggr(
    float* __restrict__ x, __half* __restrict__ xh, float* __restrict__ aggr,
    const int* __restrict__ deg, const float* __restrict__ lg,
    const float* __restrict__ lb)
{
    __shared__ float s1[4], s2[4];
    int n = blockIdx.x, h = threadIdx.x;
    float c = (float)deg[n]; if (c < 1.0f) c = 1.0f;
    float t = x[n * 128 + h] + aggr[n * 128 + h] / c;
    aggr[n * 128 + h] = 0.0f;
    float mean, var;
    ln_stats128(t, mean, var, s1, s2);
    float o = (t - mean) * rsqrtf(var + 1e-5f) * lg[h] + lb[h];
    x[n * 128 + h] = o;
    xh[n * 128 + h] = __float2half_rn(o);
}

// ---------------- graph pooling ----------------
__global__ __launch_bounds__(128) void k_pool(
    const float* __restrict__ x, const int* __restrict__ bm,
    float* __restrict__ pool, float* __restrict__ gcnt)
{
    int n = blockIdx.x, h = threadIdx.x;
    int g = bm[n];
    atomicAdd(&pool[g * 128 + h], x[n * 128 + h]);
    if (h == 0) atomicAdd(&gcnt[g], 1.0f);
}

// ---------------- output MLP ----------------
__global__ __launch_bounds__(128) void k_head(
    const float* __restrict__ pool, const float* __restrict__ gcnt,
    const float* __restrict__ w1, const float* __restrict__ b1,
    const float* __restrict__ w2, const float* __restrict__ b2,
    const float* __restrict__ w3, const float* __restrict__ b3,
    float* __restrict__ out)
{
    __shared__ float c[128], h1[128], h2[64];
    int g = blockIdx.x, h = threadIdx.x;
    float gc = gcnt[g]; if (gc < 1.0f) gc = 1.0f;
    c[h] = pool[g * 128 + h] / gc;
    __syncthreads();
    float a = b1[h];
    #pragma unroll 8
    for (int k = 0; k < 128; k++) a = fmaf(c[k], __ldg(&w1[k * 128 + h]), a);
    h1[h] = silu_f(a);
    __syncthreads();
    if (h < 64) {
        float a2 = b2[h];
        #pragma unroll 8
        for (int k = 0; k < 128; k++) a2 = fmaf(h1[k], __ldg(&w2[k * 64 + h]), a2);
        h2[h] = silu_f(a2);
    }
    __syncthreads();
    if (h < 3) {
        float a3 = b3[h];
        #pragma unroll
        for (int k = 0; k < 64; k++) a3 = fmaf(h2[k], __ldg(&w3[k * 3 + h]), a3);
        out[g * 3 + h] = a3;
    }
}

static inline int ceildiv(int a, int b) { return (a + b - 1) / b; }

extern "C" void kernel_launch(void* const* d_in, const int* in_sizes, int n_in,
                              void* d_out, int out_size)
{
    const float* atom_fea = (const float*)d_in[0];
    const float* nbr_fea  = (const float*)d_in[1];
    const int*   nbr_idx  = (const int*)  d_in[2];
    const int*   batch    = (const int*)  d_in[3];
    const float* emb_w    = (const float*)d_in[4];
    const float* emb_b    = (const float*)d_in[5];
    const float* emb_ln_g = (const float*)d_in[6];
    const float* emb_ln_b = (const float*)d_in[7];
    const float* edge_w   = (const float*)d_in[8];
    const float* edge_b   = (const float*)d_in[9];
    const float* conv_w1  = (const float*)d_in[10];
    const float* conv_b1  = (const float*)d_in[11];
    const float* conv_w2  = (const float*)d_in[12];
    const float* conv_b2  = (const float*)d_in[13];
    const float* ln_g     = (const float*)d_in[14];
    const float* ln_b     = (const float*)d_in[15];
    const float* out_w1   = (const float*)d_in[16];
    const float* out_b1   = (const float*)d_in[17];
    const float* out_w2   = (const float*)d_in[18];
    const float* out_b2   = (const float*)d_in[19];
    const float* out_w3   = (const float*)d_in[20];
    const float* out_b3   = (const float*)d_in[21];
    float* out = (float*)d_out;

    float *x, *aggr, *pool, *gcnt;
    __half *xh, *eh, *xw;
    int *deg, *cur, *off, *pos, *srcs, *dsts;
    cudaGetSymbolAddress((void**)&x,    g_x);
    cudaGetSymbolAddress((void**)&xh,   g_xh);
    cudaGetSymbolAddress((void**)&eh,   g_eh);
    cudaGetSymbolAddress((void**)&xw,   g_xw);
    cudaGetSymbolAddress((void**)&aggr, g_aggr);
    cudaGetSymbolAddress((void**)&pool, g_pool);
    cudaGetSymbolAddress((void**)&gcnt, g_gcnt);
    cudaGetSymbolAddress((void**)&deg,  g_deg);
    cudaGetSymbolAddress((void**)&cur,  g_cur);
    cudaGetSymbolAddress((void**)&off,  g_off);
    cudaGetSymbolAddress((void**)&pos,  g_pos);
    cudaGetSymbolAddress((void**)&srcs, g_srcs);
    cudaGetSymbolAddress((void**)&dsts, g_dsts);

    static int attr_set = 0;
    if (!attr_set) {
        cudaFuncSetAttribute(k_conv,
                             cudaFuncAttributeMaxDynamicSharedMemorySize, CV_SMEM);
        cudaFuncSetAttribute(k_xw,
                             cudaFuncAttributeMaxDynamicSharedMemorySize, XW_SMEM);
        attr_set = 1;
    }

    cudaMemsetAsync(deg,  0, N_NODES * sizeof(int), 0);
    cudaMemsetAsync(cur,  0, N_NODES * sizeof(int), 0);
    cudaMemsetAsync(aggr, 0, N_NODES * 128 * sizeof(float), 0);
    cudaMemsetAsync(pool, 0, N_GRAPHS * 128 * sizeof(float), 0);
    cudaMemsetAsync(gcnt, 0, N_GRAPHS * sizeof(float), 0);

    k_node_embed<<<N_NODES, 128>>>(atom_fea, emb_w, emb_b, emb_ln_g, emb_ln_b, x, xh);
    k_deg<<<ceildiv(N_EDGES, 256), 256>>>(nbr_idx, deg, N_EDGES);
    k_scan<<<1, 1024>>>(deg, off);
    k_scatter<<<ceildiv(N_EDGES, 256), 256>>>(nbr_idx, off, cur, pos, srcs, dsts);
    k_edge_embed<<<N_EDGES / 64, 128>>>(nbr_fea, edge_w, edge_b, pos, eh);

    for (int i = 0; i < NLAYERS; i++) {
        const float* W1a = conv_w1 + (long)i * 256 * 256;
        const float* W1b = W1a + 128 * 256;
        const float* W2  = conv_w2 + (long)i * 256 * 128;
        const float* b1  = conv_b1 + (long)i * 256;
        const float* b2  = conv_b2 + (long)i * 128;

        k_xw<<<ceildiv(N_NODES, 128), 512, XW_SMEM>>>(xh, W1a, b1, xw);
        k_conv<<<152, 512, CV_SMEM>>>(eh, W1b, W2, xw, b2, srcs, dsts, aggr);
        k_ln_aggr<<<N_NODES, 128>>>(x, xh, aggr, deg, ln_g + i * 128, ln_b + i * 128);
    }

    k_pool<<<N_NODES, 128>>>(x, batch, pool, gcnt);
    k_head<<<N_GRAPHS, 128>>>(pool, gcnt, out_w1, out_b1, out_w2, out_b2,
                              out_w3, out_b3, out);
    (void)in_sizes; (void)n_in; (void)out_size;
}

// round 6
// speedup vs baseline: 5.9009x; 1.4957x over previous
#include <cuda_runtime.h>
#include <cuda_fp16.h>
#include <cstdint>

#define N_NODES 50000
#define N_EDGES 800000
#define N_GRAPHS 1024
#define NLAYERS 5
#define TEDG 32
#define N_UNITS (N_EDGES / TEDG)   // 25000

// ---------------- scratch (device globals; no allocation allowed) ----------------
__device__ __align__(16) float  g_x[N_NODES * 128];
__device__ __align__(16) __half g_xh[N_NODES * 128];
__device__ __align__(16) __half g_eh[N_EDGES * 128];     // dst-sorted edge features
__device__ __align__(16) __half g_xw[N_NODES * 256];     // fp16 XW = x@W1a + b1
__device__ __align__(16) float  g_aggr[N_NODES * 128];
__device__ __align__(16) float  g_pool[N_GRAPHS * 128];
__device__ __align__(16) float  g_gcnt[N_GRAPHS];
__device__ __align__(16) uint2  g_w1p[NLAYERS * 8192];   // W1b fragment-packed
__device__ __align__(16) uint2  g_w2p[NLAYERS * 8192];   // W2 fragment-packed
__device__ int g_deg[N_NODES];
__device__ int g_cur[N_NODES];
__device__ int g_off[N_NODES];
__device__ int g_pos[N_EDGES];
__device__ int g_srcs[N_EDGES];
__device__ int g_dsts[N_EDGES];

__device__ __forceinline__ float silu_f(float v) {
    return __fdividef(v, 1.0f + __expf(-v));
}

__device__ __forceinline__ uint32_t sptr(const void* p) {
    return (uint32_t)__cvta_generic_to_shared(p);
}
__device__ __forceinline__ uint32_t swz(int row, int c8, int rowBytes) {
    return (uint32_t)(row * rowBytes + (((c8 ^ (row & 7)) << 4)));
}
__device__ __forceinline__ void ldsm_x4(uint32_t* r, uint32_t addr) {
    asm volatile("ldmatrix.sync.aligned.m8n8.x4.shared.b16 {%0,%1,%2,%3}, [%4];\n"
                 : "=r"(r[0]), "=r"(r[1]), "=r"(r[2]), "=r"(r[3]) : "r"(addr));
}
__device__ __forceinline__ void ldsm_x4_t(uint32_t* r, uint32_t addr) {
    asm volatile("ldmatrix.sync.aligned.m8n8.x4.trans.shared.b16 {%0,%1,%2,%3}, [%4];\n"
                 : "=r"(r[0]), "=r"(r[1]), "=r"(r[2]), "=r"(r[3]) : "r"(addr));
}
__device__ __forceinline__ void mma_16816(float* c, const uint32_t* a, const uint32_t* b) {
    asm volatile(
        "mma.sync.aligned.m16n8k16.row.col.f32.f16.f16.f32 "
        "{%0,%1,%2,%3}, {%4,%5,%6,%7}, {%8,%9}, {%0,%1,%2,%3};\n"
        : "+f"(c[0]), "+f"(c[1]), "+f"(c[2]), "+f"(c[3])
        : "r"(a[0]), "r"(a[1]), "r"(a[2]), "r"(a[3]), "r"(b[0]), "r"(b[1]));
}
__device__ __forceinline__ void red2(float* p, float a, float b) {
    asm volatile("red.global.add.v2.f32 [%0], {%1,%2};" :: "l"(p), "f"(a), "f"(b) : "memory");
}
#define CP_ASYNC16(sdst, gsrc) \
    asm volatile("cp.async.cg.shared.global [%0], [%1], 16;" :: "r"(sdst), "l"(gsrc) : "memory")
#define CP_COMMIT() asm volatile("cp.async.commit_group;" ::: "memory")
#define CP_WAIT0()  asm volatile("cp.async.wait_group 0;" ::: "memory")

// block = 128 threads (4 warps). mean/var over the block.
__device__ __forceinline__ void ln_stats128(float v, float& mean, float& var,
                                            float* s1, float* s2) {
    float a = v, b = v * v;
    #pragma unroll
    for (int o = 16; o > 0; o >>= 1) {
        a += __shfl_down_sync(0xffffffffu, a, o);
        b += __shfl_down_sync(0xffffffffu, b, o);
    }
    int w = threadIdx.x >> 5;
    if ((threadIdx.x & 31) == 0) { s1[w] = a; s2[w] = b; }
    __syncthreads();
    if (threadIdx.x == 0) {
        s1[0] = s1[0] + s1[1] + s1[2] + s1[3];
        s2[0] = s2[0] + s2[1] + s2[2] + s2[3];
    }
    __syncthreads();
    mean = s1[0] * (1.0f / 128.0f);
    var  = s2[0] * (1.0f / 128.0f) - mean * mean;
}

// ---------------- node embedding ----------------
__global__ __launch_bounds__(128) void k_node_embed(
    const float* __restrict__ atom, const float* __restrict__ w,
    const float* __restrict__ b, const float* __restrict__ lg,
    const float* __restrict__ lb, float* __restrict__ x, __half* __restrict__ xh)
{
    __shared__ float s1[4], s2[4], sa[4];
    int n = blockIdx.x, h = threadIdx.x;
    if (h < 4) sa[h] = atom[n * 4 + h];
    __syncthreads();
    float v = b[h];
    #pragma unroll
    for (int k = 0; k < 4; k++) v = fmaf(sa[k], __ldg(&w[k * 128 + h]), v);
    float mean, var;
    ln_stats128(v, mean, var, s1, s2);
    float y = (v - mean) * rsqrtf(var + 1e-5f) * lg[h] + lb[h];
    float o = silu_f(y);
    x[n * 128 + h] = o;
    xh[n * 128 + h] = __float2half_rn(o);
}

// ---------------- degree count ----------------
__global__ void k_deg(const int* __restrict__ idx, int* __restrict__ deg, int nE) {
    int i = blockIdx.x * blockDim.x + threadIdx.x;
    if (i < nE) atomicAdd(&deg[idx[2 * i + 1]], 1);
}

// ---------------- exclusive prefix scan over deg (one block) ----------------
#define SCAN_CH 49
__global__ __launch_bounds__(1024) void k_scan(const int* __restrict__ deg,
                                               int* __restrict__ off)
{
    __shared__ int wsum[32];
    int tid = threadIdx.x, lane = tid & 31, w = tid >> 5;
    int base = tid * SCAN_CH;
    int s = 0;
    for (int j = 0; j < SCAN_CH; j++) {
        int ix = base + j;
        if (ix < N_NODES) s += deg[ix];
    }
    int incl = s;
    #pragma unroll
    for (int o = 1; o < 32; o <<= 1) {
        int t2 = __shfl_up_sync(0xffffffffu, incl, o);
        if (lane >= o) incl += t2;
    }
    if (lane == 31) wsum[w] = incl;
    __syncthreads();
    if (w == 0) {
        int v = wsum[lane];
        #pragma unroll
        for (int o = 1; o < 32; o <<= 1) {
            int t2 = __shfl_up_sync(0xffffffffu, v, o);
            if (lane >= o) v += t2;
        }
        wsum[lane] = v;
    }
    __syncthreads();
    int run = incl - s + (w > 0 ? wsum[w - 1] : 0);
    for (int j = 0; j < SCAN_CH; j++) {
        int ix = base + j;
        if (ix < N_NODES) { off[ix] = run; run += deg[ix]; }
    }
}

// ---------------- edge scatter (counting sort by dst) ----------------
__global__ void k_scatter(const int* __restrict__ nbr, const int* __restrict__ off,
                          int* __restrict__ cur, int* __restrict__ pos,
                          int* __restrict__ srcs, int* __restrict__ dsts)
{
    int i = blockIdx.x * blockDim.x + threadIdx.x;
    if (i < N_EDGES) {
        int d = nbr[2 * i + 1];
        int p = off[d] + atomicAdd(&cur[d], 1);
        pos[i] = p;
        srcs[p] = nbr[2 * i];
        dsts[p] = d;
    }
}

// ---------------- edge embedding (vectorized, writes permuted rows) ----------------
__global__ __launch_bounds__(128) void k_edge_embed(
    const float* __restrict__ nbr, const float* __restrict__ w,
    const float* __restrict__ b, const int* __restrict__ pos, __half* __restrict__ e)
{
    __shared__ float snbr[64][44];
    __shared__ int spos[64];
    const int h = threadIdx.x;
    const long e0 = (long)blockIdx.x * 64;
    float wr[44];
    #pragma unroll
    for (int k = 0; k < 41; k++) wr[k] = w[k * 128 + h];
    wr[41] = wr[42] = wr[43] = 0.0f;
    if (h < 64) {
        snbr[h][41] = 0.0f; snbr[h][42] = 0.0f; snbr[h][43] = 0.0f;
        spos[h] = pos[e0 + h];
    }
    const float* base = nbr + e0 * 41;
    for (int t = h; t < 64 * 41; t += 128) snbr[t / 41][t % 41] = base[t];
    float bb = b[h];
    __syncthreads();
    #pragma unroll 2
    for (int r = 0; r < 64; r++) {
        float acc = bb;
        #pragma unroll
        for (int k4 = 0; k4 < 11; k4++) {
            float4 s = *(const float4*)&snbr[r][k4 * 4];
            acc = fmaf(s.x, wr[k4 * 4 + 0], acc);
            acc = fmaf(s.y, wr[k4 * 4 + 1], acc);
            acc = fmaf(s.z, wr[k4 * 4 + 2], acc);
            acc = fmaf(s.w, wr[k4 * 4 + 3], acc);
        }
        e[(long)spos[r] * 128 + h] = __float2half_rn(silu_f(acc));
    }
}

// ---------------- weight fragment packing (all layers, once) ----------------
// m16n8k16 B-fragment layout: lane = 4*g + t holds, for n-tile nt and k-step ks:
//   reg0 = half2( B[16ks+2t][nt*8+g], B[16ks+2t+1][nt*8+g] )
//   reg1 = half2( B[16ks+2t+8][nt*8+g], B[16ks+2t+9][nt*8+g] )
__global__ __launch_bounds__(256) void k_cvt(
    const float* __restrict__ w1, const float* __restrict__ w2,
    uint2* __restrict__ w1p, uint2* __restrict__ w2p)
{
    int i = blockIdx.x * 256 + threadIdx.x;
    if (i >= NLAYERS * 8192) return;
    int lane = i & 31;
    int t = lane & 3, g = lane >> 2;
    {   // W1P: B[k][n] = conv_w1[(128+k)*256 + n]; 8 ks x 32 nt
        int r = i >> 5;
        int nt = r & 31; r >>= 5;
        int ks = r & 7;  int layer = r >> 3;
        const float* W = w1 + (long)layer * 65536;
        int n = nt * 8 + g, k0 = ks * 16 + 2 * t;
        __half2 a = __floats2half2_rn(W[(128 + k0) * 256 + n], W[(129 + k0) * 256 + n]);
        __half2 b = __floats2half2_rn(W[(136 + k0) * 256 + n], W[(137 + k0) * 256 + n]);
        w1p[i] = make_uint2(*(uint32_t*)&a, *(uint32_t*)&b);
    }
    {   // W2P: B[k][n] = conv_w2[k*128 + n]; 16 ks x 16 nt
        int r = i >> 5;
        int nt = r & 15; r >>= 4;
        int ks = r & 15; int layer = r >> 4;
        const float* W = w2 + (long)layer * 32768;
        int n = nt * 8 + g, k0 = ks * 16 + 2 * t;
        __half2 a = __floats2half2_rn(W[k0 * 128 + n],       W[(k0 + 1) * 128 + n]);
        __half2 b = __floats2half2_rn(W[(k0 + 8) * 128 + n], W[(k0 + 9) * 128 + n]);
        w2p[i] = make_uint2(*(uint32_t*)&a, *(uint32_t*)&b);
    }
}

// ================= k_xw: XW = x @ W1a + b1 (HMMA, fp16 output) =================
#define XW_SE 0
#define XW_SW 32768
#define XW_SMEM 98304

template <int KR, int NC>
__device__ __forceinline__ void wload(char* sdst, const float* __restrict__ W, int tid) {
    const float4* wv = (const float4*)W;
    constexpr int NV = NC / 4;
    #pragma unroll 4
    for (int i = tid; i < KR * NV; i += 512) {
        int k = i / NV, n4 = (i % NV) * 4;
        float4 v = __ldg(&wv[i]);
        __half2 a = __floats2half2_rn(v.x, v.y);
        __half2 b = __floats2half2_rn(v.z, v.w);
        char* p = sdst + swz(k, n4 >> 3, NC * 2) + ((n4 & 7) << 1);
        *(uint32_t*)p = *(uint32_t*)&a;
        *(uint32_t*)(p + 4) = *(uint32_t*)&b;
    }
}

__global__ __launch_bounds__(512) void k_xw(
    const __half* __restrict__ Xh, const float* __restrict__ W1a,
    const float* __restrict__ b1, __half* __restrict__ XW)
{
    extern __shared__ char sm[];
    const int tid = threadIdx.x, lane = tid & 31, warp = tid >> 5;
    const int wm = (warp & 3) * 32, wn = warp >> 2;
    const int g = lane >> 2, t = lane & 3;
    const uint32_t sbase = sptr(sm);
    const long rowBase = (long)blockIdx.x * 128;

    wload<128, 256>(sm + XW_SW, W1a, tid);
    {
        int row = tid >> 2, cb = (tid & 3) * 4;
        long grow = rowBase + row;
        if (grow >= N_NODES) grow = N_NODES - 1;
        const uint4* p = (const uint4*)(Xh + grow * 128) + cb;
        #pragma unroll
        for (int j = 0; j < 4; j++)
            *(uint4*)(sm + XW_SE + swz(row, cb + j, 256)) = __ldg(p + j);
    }
    __syncthreads();

    float acc[2][8][4];
    #pragma unroll
    for (int mi = 0; mi < 2; mi++)
        #pragma unroll
        for (int nj = 0; nj < 8; nj++)
            #pragma unroll
            for (int q = 0; q < 4; q++) acc[mi][nj][q] = 0.0f;

    for (int ks = 0; ks < 8; ks++) {
        uint32_t af[2][4], bf[8][2];
        #pragma unroll
        for (int mi = 0; mi < 2; mi++)
            ldsm_x4(af[mi], sbase + XW_SE +
                    swz(wm + mi * 16 + (lane & 15), ks * 2 + (lane >> 4), 256));
        #pragma unroll
        for (int np = 0; np < 4; np++) {
            uint32_t r4[4];
            ldsm_x4_t(r4, sbase + XW_SW +
                      swz(ks * 16 + (lane & 15), wn * 8 + np * 2 + (lane >> 4), 512));
            bf[np * 2 + 0][0] = r4[0]; bf[np * 2 + 0][1] = r4[1];
            bf[np * 2 + 1][0] = r4[2]; bf[np * 2 + 1][1] = r4[3];
        }
        #pragma unroll
        for (int mi = 0; mi < 2; mi++)
            #pragma unroll
            for (int nj = 0; nj < 8; nj++)
                mma_16816(acc[mi][nj], af[mi], bf[nj]);
    }

    #pragma unroll
    for (int mi = 0; mi < 2; mi++) {
        long g0 = rowBase + wm + mi * 16 + g, g1 = g0 + 8;
        #pragma unroll
        for (int nj = 0; nj < 8; nj++) {
            int col = wn * 64 + nj * 8 + 2 * t;
            float2 bb = *(const float2*)(b1 + col);
            if (g0 < N_NODES) {
                __half2 h = __floats2half2_rn(acc[mi][nj][0] + bb.x, acc[mi][nj][1] + bb.y);
                *(uint32_t*)(XW + g0 * 256 + col) = *(uint32_t*)&h;
            }
            if (g1 < N_NODES) {
                __half2 h = __floats2half2_rn(acc[mi][nj][2] + bb.x, acc[mi][nj][3] + bb.y);
                *(uint32_t*)(XW + g1 * 256 + col) = *(uint32_t*)&h;
            }
        }
    }
}

// ================= k_conv: 32-edge tiles, 256 threads, 3 CTAs/SM =================
// smem: E 32x256B = 8192 @0 ; M1/XW 32x512B = 16384 @8192 ; idx 256B @24576
#define CE 0
#define CM 8192
#define CI 24576
#define CONV_SMEM 24832

__global__ __launch_bounds__(256, 3) void k_conv(
    const __half* __restrict__ E, const uint2* __restrict__ W1P,
    const uint2* __restrict__ W2P, const __half* __restrict__ XW,
    const float* __restrict__ b2, const int* __restrict__ srcs,
    const int* __restrict__ dsts, float* __restrict__ aggr)
{
    extern __shared__ char sm[];
    const int tid = threadIdx.x, lane = tid & 31, wn = tid >> 5;   // 8 warps
    const int g = lane >> 2, t = lane & 3;
    const uint32_t sbase = sptr(sm);
    int* sSrc = (int*)(sm + CI);
    int* sDst = sSrc + 32;
    const long ebase = (long)blockIdx.x * TEDG;

    // ---- stage E tile (32x128 f16) + indices ----
    #pragma unroll
    for (int p = 0; p < 2; p++) {
        int i = tid + p * 256;
        int row = i >> 4, c8 = i & 15;
        CP_ASYNC16(sbase + CE + swz(row, c8, 256), E + (ebase + row) * 128 + c8 * 8);
    }
    if (tid < 8) CP_ASYNC16(sbase + CI + tid * 16, srcs + ebase + tid * 4);
    else if (tid < 16) CP_ASYNC16(sbase + CI + 128 + (tid - 8) * 16, dsts + ebase + (tid - 8) * 4);
    CP_COMMIT();
    CP_WAIT0();
    __syncthreads();   // S1

    // ---- issue XW gather (32 rows x 256 f16 = 32KB) ----
    #pragma unroll
    for (int p = 0; p < 4; p++) {
        int i = tid + p * 256;
        int row = i >> 5, c8 = i & 31;
        CP_ASYNC16(sbase + CM + swz(row, c8, 512),
                   XW + (long)sSrc[row] * 256 + c8 * 8);
    }
    CP_COMMIT();

    // ---- phase 1: D1 = E @ W1b  (32 x 256, K=128) ----
    float acc[2][4][4];
    #pragma unroll
    for (int mi = 0; mi < 2; mi++)
        #pragma unroll
        for (int nj = 0; nj < 4; nj++)
            #pragma unroll
            for (int q = 0; q < 4; q++) acc[mi][nj][q] = 0.0f;

    #pragma unroll
    for (int ks = 0; ks < 8; ks++) {
        uint32_t af[2][4];
        #pragma unroll
        for (int mi = 0; mi < 2; mi++)
            ldsm_x4(af[mi], sbase + CE +
                    swz(mi * 16 + (lane & 15), ks * 2 + (lane >> 4), 256));
        uint2 bf[4];
        const uint2* bp = W1P + (ks * 32 + wn * 4) * 32 + lane;
        #pragma unroll
        for (int nj = 0; nj < 4; nj++) bf[nj] = __ldg(bp + nj * 32);
        #pragma unroll
        for (int mi = 0; mi < 2; mi++)
            #pragma unroll
            for (int nj = 0; nj < 4; nj++)
                mma_16816(acc[mi][nj], af[mi], (uint32_t*)&bf[nj]);
    }
    CP_WAIT0();
    __syncthreads();   // S2: XW staged, phase-1 E reads done

    // ---- epilogue 1: M1 = silu(D1 + XW_staged), in-place fp16 in CM ----
    #pragma unroll
    for (int mi = 0; mi < 2; mi++) {
        int r0 = mi * 16 + g, r1 = r0 + 8;
        #pragma unroll
        for (int nj = 0; nj < 4; nj++) {
            int col = wn * 32 + nj * 8 + 2 * t;
            uint32_t a0o = CM + swz(r0, col >> 3, 512) + ((col & 7) << 1);
            uint32_t a1o = CM + swz(r1, col >> 3, 512) + ((col & 7) << 1);
            float2 f0 = __half22float2(*(__half2*)(sm + a0o));
            float2 f1 = __half22float2(*(__half2*)(sm + a1o));
            __half2 h0 = __floats2half2_rn(silu_f(acc[mi][nj][0] + f0.x),
                                           silu_f(acc[mi][nj][1] + f0.y));
            __half2 h1 = __floats2half2_rn(silu_f(acc[mi][nj][2] + f1.x),
                                           silu_f(acc[mi][nj][3] + f1.y));
            *(__half2*)(sm + a0o) = h0;
            *(__half2*)(sm + a1o) = h1;
        }
    }
    __syncthreads();   // S3: M1 complete

    // ---- phase 2: D2 = M1 @ W2  (32 x 128, K=256) ----
    float ac2[2][2][4];
    #pragma unroll
    for (int mi = 0; mi < 2; mi++)
        #pragma unroll
        for (int nj = 0; nj < 2; nj++)
            #pragma unroll
            for (int q = 0; q < 4; q++) ac2[mi][nj][q] = 0.0f;

    #pragma unroll
    for (int ks = 0; ks < 16; ks++) {
        uint32_t af[2][4];
        #pragma unroll
        for (int mi = 0; mi < 2; mi++)
            ldsm_x4(af[mi], sbase + CM +
                    swz(mi * 16 + (lane & 15), ks * 2 + (lane >> 4), 512));
        uint2 bf[2];
        const uint2* bp = W2P + (ks * 16 + wn * 2) * 32 + lane;
        #pragma unroll
        for (int nj = 0; nj < 2; nj++) bf[nj] = __ldg(bp + nj * 32);
        #pragma unroll
        for (int mi = 0; mi < 2; mi++)
            #pragma unroll
            for (int nj = 0; nj < 2; nj++)
                mma_16816(ac2[mi][nj], af[mi], (uint32_t*)&bf[nj]);
    }

    // ---- epilogue 2a: stage silu(D2 + b2) fp16 into CE (dead E region) ----
    #pragma unroll
    for (int mi = 0; mi < 2; mi++) {
        int r0 = mi * 16 + g, r1 = r0 + 8;
        #pragma unroll
        for (int nj = 0; nj < 2; nj++) {
            int col = wn * 16 + nj * 8 + 2 * t;
            float2 bb = __ldg((const float2*)(b2 + col));
            __half2 h0 = __floats2half2_rn(silu_f(ac2[mi][nj][0] + bb.x),
                                           silu_f(ac2[mi][nj][1] + bb.y));
            __half2 h1 = __floats2half2_rn(silu_f(ac2[mi][nj][2] + bb.x),
                                           silu_f(ac2[mi][nj][3] + bb.y));
            *(__half2*)(sm + CE + swz(r0, col >> 3, 256) + ((col & 7) << 1)) = h0;
            *(__half2*)(sm + CE + swz(r1, col >> 3, 256) + ((col & 7) << 1)) = h1;
        }
    }
    __syncthreads();   // S4

    // ---- epilogue 2b: segmented reduction over dst-sorted rows ----
    {
        int c = tid & 63;            // column pair: cols 2c, 2c+1
        int q = tid >> 6;            // rows 8q .. 8q+7
        int col = 2 * c;
        float ax = 0.0f, ay = 0.0f;
        int prev = sDst[8 * q];
        #pragma unroll
        for (int r8 = 0; r8 < 8; r8++) {
            int r = 8 * q + r8;
            int d = sDst[r];
            if (d != prev) {
                red2(aggr + (long)prev * 128 + col, ax, ay);
                ax = 0.0f; ay = 0.0f; prev = d;
            }
            uint32_t hv = *(uint32_t*)(sm + CE + swz(r, col >> 3, 256) +
                                       ((col & 7) << 1));
            float2 v = __half22float2(*(__half2*)&hv);
            ax += v.x; ay += v.y;
        }
        red2(aggr + (long)prev * 128 + col, ax, ay);
    }
}

// ---------------- x = LN(x + aggr/cnt), zero aggr, emit fp16 ----------------
__global__ __launch_bounds__(128) void k_ln_aggr(
    float* __restrict__ x, __half* __restrict__ xh, float* __restrict__ aggr,
    const int* __restrict__ deg, const float* __restrict__ lg,
    const float* __restrict__ lb)
{
    __shared__ float s1[4], s2[4];
    int n = blockIdx.x, h = threadIdx.x;
    float c = (float)deg[n]; if (c < 1.0f) c = 1.0f;
    float t = x[n * 128 + h] + aggr[n * 128 + h] / c;
    aggr[n * 128 + h] = 0.0f;
    float mean, var;
    ln_stats128(t, mean, var, s1, s2);
    float o = (t - mean) * rsqrtf(var + 1e-5f) * lg[h] + lb[h];
    x[n * 128 + h] = o;
    xh[n * 128 + h] = __float2half_rn(o);
}

// ---------------- graph pooling ----------------
__global__ __launch_bounds__(128) void k_pool(
    const float* __restrict__ x, const int* __restrict__ bm,
    float* __restrict__ pool, float* __restrict__ gcnt)
{
    int n = blockIdx.x, h = threadIdx.x;
    int g = bm[n];
    atomicAdd(&pool[g * 128 + h], x[n * 128 + h]);
    if (h == 0) atomicAdd(&gcnt[g], 1.0f);
}

// ---------------- output MLP ----------------
__global__ __launch_bounds__(128) void k_head(
    const float* __restrict__ pool, const float* __restrict__ gcnt,
    const float* __restrict__ w1, const float* __restrict__ b1,
    const float* __restrict__ w2, const float* __restrict__ b2,
    const float* __restrict__ w3, const float* __restrict__ b3,
    float* __restrict__ out)
{
    __shared__ float c[128], h1[128], h2[64];
    int g = blockIdx.x, h = threadIdx.x;
    float gc = gcnt[g]; if (gc < 1.0f) gc = 1.0f;
    c[h] = pool[g * 128 + h] / gc;
    __syncthreads();
    float a = b1[h];
    #pragma unroll 8
    for (int k = 0; k < 128; k++) a = fmaf(c[k], __ldg(&w1[k * 128 + h]), a);
    h1[h] = silu_f(a);
    __syncthreads();
    if (h < 64) {
        float a2 = b2[h];
        #pragma unroll 8
        for (int k = 0; k < 128; k++) a2 = fmaf(h1[k], __ldg(&w2[k * 64 + h]), a2);
        h2[h] = silu_f(a2);
    }
    __syncthreads();
    if (h < 3) {
        float a3 = b3[h];
        #pragma unroll
        for (int k = 0; k < 64; k++) a3 = fmaf(h2[k], __ldg(&w3[k * 3 + h]), a3);
        out[g * 3 + h] = a3;
    }
}

static inline int ceildiv(int a, int b) { return (a + b - 1) / b; }

extern "C" void kernel_launch(void* const* d_in, const int* in_sizes, int n_in,
                              void* d_out, int out_size)
{
    const float* atom_fea = (const float*)d_in[0];
    const float* nbr_fea  = (const float*)d_in[1];
    const int*   nbr_idx  = (const int*)  d_in[2];
    const int*   batch    = (const int*)  d_in[3];
    const float* emb_w    = (const float*)d_in[4];
    const float* emb_b    = (const float*)d_in[5];
    const float* emb_ln_g = (const float*)d_in[6];
    const float* emb_ln_b = (const float*)d_in[7];
    const float* edge_w   = (const float*)d_in[8];
    const float* edge_b   = (const float*)d_in[9];
    const float* conv_w1  = (const float*)d_in[10];
    const float* conv_b1  = (const float*)d_in[11];
    const float* conv_w2  = (const float*)d_in[12];
    const float* conv_b2  = (const float*)d_in[13];
    const float* ln_g     = (const float*)d_in[14];
    const float* ln_b     = (const float*)d_in[15];
    const float* out_w1   = (const float*)d_in[16];
    const float* out_b1   = (const float*)d_in[17];
    const float* out_w2   = (const float*)d_in[18];
    const float* out_b2   = (const float*)d_in[19];
    const float* out_w3   = (const float*)d_in[20];
    const float* out_b3   = (const float*)d_in[21];
    float* out = (float*)d_out;

    float *x, *aggr, *pool, *gcnt;
    __half *xh, *eh, *xw;
    uint2 *w1p, *w2p;
    int *deg, *cur, *off, *pos, *srcs, *dsts;
    cudaGetSymbolAddress((void**)&x,    g_x);
    cudaGetSymbolAddress((void**)&xh,   g_xh);
    cudaGetSymbolAddress((void**)&eh,   g_eh);
    cudaGetSymbolAddress((void**)&xw,   g_xw);
    cudaGetSymbolAddress((void**)&aggr, g_aggr);
    cudaGetSymbolAddress((void**)&pool, g_pool);
    cudaGetSymbolAddress((void**)&gcnt, g_gcnt);
    cudaGetSymbolAddress((void**)&w1p,  g_w1p);
    cudaGetSymbolAddress((void**)&w2p,  g_w2p);
    cudaGetSymbolAddress((void**)&deg,  g_deg);
    cudaGetSymbolAddress((void**)&cur,  g_cur);
    cudaGetSymbolAddress((void**)&off,  g_off);
    cudaGetSymbolAddress((void**)&pos,  g_pos);
    cudaGetSymbolAddress((void**)&srcs, g_srcs);
    cudaGetSymbolAddress((void**)&dsts, g_dsts);

    static int attr_set = 0;
    if (!attr_set) {
        cudaFuncSetAttribute(k_xw,
                             cudaFuncAttributeMaxDynamicSharedMemorySize, XW_SMEM);
        attr_set = 1;
    }

    cudaMemsetAsync(deg,  0, N_NODES * sizeof(int), 0);
    cudaMemsetAsync(cur,  0, N_NODES * sizeof(int), 0);
    cudaMemsetAsync(aggr, 0, N_NODES * 128 * sizeof(float), 0);
    cudaMemsetAsync(pool, 0, N_GRAPHS * 128 * sizeof(float), 0);
    cudaMemsetAsync(gcnt, 0, N_GRAPHS * sizeof(float), 0);

    k_node_embed<<<N_NODES, 128>>>(atom_fea, emb_w, emb_b, emb_ln_g, emb_ln_b, x, xh);
    k_deg<<<ceildiv(N_EDGES, 256), 256>>>(nbr_idx, deg, N_EDGES);
    k_scan<<<1, 1024>>>(deg, off);
    k_scatter<<<ceildiv(N_EDGES, 256), 256>>>(nbr_idx, off, cur, pos, srcs, dsts);
    k_edge_embed<<<N_EDGES / 64, 128>>>(nbr_fea, edge_w, edge_b, pos, eh);
    k_cvt<<<ceildiv(NLAYERS * 8192, 256), 256>>>(conv_w1, conv_w2, w1p, w2p);

    for (int i = 0; i < NLAYERS; i++) {
        const float* W1a = conv_w1 + (long)i * 256 * 256;
        const float* b1  = conv_b1 + (long)i * 256;
        const float* b2  = conv_b2 + (long)i * 128;

        k_xw<<<ceildiv(N_NODES, 128), 512, XW_SMEM>>>(xh, W1a, b1, xw);
        k_conv<<<N_UNITS, 256, CONV_SMEM>>>(eh, w1p + (long)i * 8192,
                                            w2p + (long)i * 8192, xw, b2,
                                            srcs, dsts, aggr);
        k_ln_aggr<<<N_NODES, 128>>>(x, xh, aggr, deg, ln_g + i * 128, ln_b + i * 128);
    }

    k_pool<<<N_NODES, 128>>>(x, batch, pool, gcnt);
    k_head<<<N_GRAPHS, 128>>>(pool, gcnt, out_w1, out_b1, out_w2, out_b2,
                              out_w3, out_b3, out);
    (void)in_sizes; (void)n_in; (void)out_size;
}

// round 7
// speedup vs baseline: 5.9364x; 1.0060x over previous
#include <cuda_runtime.h>
#include <cuda_fp16.h>
#include <cstdint>

#define N_NODES 50000
#define N_EDGES 800000
#define N_GRAPHS 1024
#define NLAYERS 5
#define TEDG 32
#define N_UNITS (N_EDGES / TEDG)   // 25000

// ---------------- scratch (device globals; no allocation allowed) ----------------
__device__ __align__(16) float  g_x[N_NODES * 128];
__device__ __align__(16) __half g_xh[N_NODES * 128];
__device__ __align__(16) __half g_eh[N_EDGES * 128];     // dst-sorted edge features
__device__ __align__(16) __half g_xw[N_NODES * 256];     // fp16 XW = x@W1a + b1
__device__ __align__(16) float  g_aggr[N_NODES * 128];
__device__ __align__(16) float  g_pool[N_GRAPHS * 128];
__device__ __align__(16) float  g_gcnt[N_GRAPHS];
__device__ __align__(16) uint2  g_w1p[NLAYERS * 8192];   // W1b fragment-packed
__device__ __align__(16) uint2  g_w2p[NLAYERS * 8192];   // W2 fragment-packed
__device__ __align__(16) uint2  g_ewp[1536];             // edge_w fragment-packed (K=48)
__device__ int g_deg[N_NODES];
__device__ int g_cur[N_NODES];
__device__ int g_off[N_NODES];
__device__ int g_pos[N_EDGES];
__device__ int g_srcs[N_EDGES];
__device__ int g_dsts[N_EDGES];

__device__ __forceinline__ float silu_f(float v) {
    return __fdividef(v, 1.0f + __expf(-v));
}

__device__ __forceinline__ uint32_t sptr(const void* p) {
    return (uint32_t)__cvta_generic_to_shared(p);
}
__device__ __forceinline__ uint32_t swz(int row, int c8, int rowBytes) {
    return (uint32_t)(row * rowBytes + (((c8 ^ (row & 7)) << 4)));
}
__device__ __forceinline__ void ldsm_x4(uint32_t* r, uint32_t addr) {
    asm volatile("ldmatrix.sync.aligned.m8n8.x4.shared.b16 {%0,%1,%2,%3}, [%4];\n"
                 : "=r"(r[0]), "=r"(r[1]), "=r"(r[2]), "=r"(r[3]) : "r"(addr));
}
__device__ __forceinline__ void ldsm_x4_t(uint32_t* r, uint32_t addr) {
    asm volatile("ldmatrix.sync.aligned.m8n8.x4.trans.shared.b16 {%0,%1,%2,%3}, [%4];\n"
                 : "=r"(r[0]), "=r"(r[1]), "=r"(r[2]), "=r"(r[3]) : "r"(addr));
}
__device__ __forceinline__ void mma_16816(float* c, const uint32_t* a, const uint32_t* b) {
    asm volatile(
        "mma.sync.aligned.m16n8k16.row.col.f32.f16.f16.f32 "
        "{%0,%1,%2,%3}, {%4,%5,%6,%7}, {%8,%9}, {%0,%1,%2,%3};\n"
        : "+f"(c[0]), "+f"(c[1]), "+f"(c[2]), "+f"(c[3])
        : "r"(a[0]), "r"(a[1]), "r"(a[2]), "r"(a[3]), "r"(b[0]), "r"(b[1]));
}
__device__ __forceinline__ void red2(float* p, float a, float b) {
    asm volatile("red.global.add.v2.f32 [%0], {%1,%2};" :: "l"(p), "f"(a), "f"(b) : "memory");
}
#define CP_ASYNC16(sdst, gsrc) \
    asm volatile("cp.async.cg.shared.global [%0], [%1], 16;" :: "r"(sdst), "l"(gsrc) : "memory")
#define CP_COMMIT() asm volatile("cp.async.commit_group;" ::: "memory")
#define CP_WAIT0()  asm volatile("cp.async.wait_group 0;" ::: "memory")
#define CP_WAIT1()  asm volatile("cp.async.wait_group 1;" ::: "memory")

// block = 128 threads (4 warps). mean/var over the block.
__device__ __forceinline__ void ln_stats128(float v, float& mean, float& var,
                                            float* s1, float* s2) {
    float a = v, b = v * v;
    #pragma unroll
    for (int o = 16; o > 0; o >>= 1) {
        a += __shfl_down_sync(0xffffffffu, a, o);
        b += __shfl_down_sync(0xffffffffu, b, o);
    }
    int w = threadIdx.x >> 5;
    if ((threadIdx.x & 31) == 0) { s1[w] = a; s2[w] = b; }
    __syncthreads();
    if (threadIdx.x == 0) {
        s1[0] = s1[0] + s1[1] + s1[2] + s1[3];
        s2[0] = s2[0] + s2[1] + s2[2] + s2[3];
    }
    __syncthreads();
    mean = s1[0] * (1.0f / 128.0f);
    var  = s2[0] * (1.0f / 128.0f) - mean * mean;
}

// ---------------- node embedding ----------------
__global__ __launch_bounds__(128) void k_node_embed(
    const float* __restrict__ atom, const float* __restrict__ w,
    const float* __restrict__ b, const float* __restrict__ lg,
    const float* __restrict__ lb, float* __restrict__ x, __half* __restrict__ xh)
{
    __shared__ float s1[4], s2[4], sa[4];
    int n = blockIdx.x, h = threadIdx.x;
    if (h < 4) sa[h] = atom[n * 4 + h];
    __syncthreads();
    float v = b[h];
    #pragma unroll
    for (int k = 0; k < 4; k++) v = fmaf(sa[k], __ldg(&w[k * 128 + h]), v);
    float mean, var;
    ln_stats128(v, mean, var, s1, s2);
    float y = (v - mean) * rsqrtf(var + 1e-5f) * lg[h] + lb[h];
    float o = silu_f(y);
    x[n * 128 + h] = o;
    xh[n * 128 + h] = __float2half_rn(o);
}

// ---------------- degree count ----------------
__global__ void k_deg(const int* __restrict__ idx, int* __restrict__ deg, int nE) {
    int i = blockIdx.x * blockDim.x + threadIdx.x;
    if (i < nE) atomicAdd(&deg[idx[2 * i + 1]], 1);
}

// ---------------- exclusive prefix scan over deg (one block) ----------------
#define SCAN_CH 49
__global__ __launch_bounds__(1024) void k_scan(const int* __restrict__ deg,
                                               int* __restrict__ off)
{
    __shared__ int wsum[32];
    int tid = threadIdx.x, lane = tid & 31, w = tid >> 5;
    int base = tid * SCAN_CH;
    int s = 0;
    for (int j = 0; j < SCAN_CH; j++) {
        int ix = base + j;
        if (ix < N_NODES) s += deg[ix];
    }
    int incl = s;
    #pragma unroll
    for (int o = 1; o < 32; o <<= 1) {
        int t2 = __shfl_up_sync(0xffffffffu, incl, o);
        if (lane >= o) incl += t2;
    }
    if (lane == 31) wsum[w] = incl;
    __syncthreads();
    if (w == 0) {
        int v = wsum[lane];
        #pragma unroll
        for (int o = 1; o < 32; o <<= 1) {
            int t2 = __shfl_up_sync(0xffffffffu, v, o);
            if (lane >= o) v += t2;
        }
        wsum[lane] = v;
    }
    __syncthreads();
    int run = incl - s + (w > 0 ? wsum[w - 1] : 0);
    for (int j = 0; j < SCAN_CH; j++) {
        int ix = base + j;
        if (ix < N_NODES) { off[ix] = run; run += deg[ix]; }
    }
}

// ---------------- edge scatter (counting sort by dst) ----------------
__global__ void k_scatter(const int* __restrict__ nbr, const int* __restrict__ off,
                          int* __restrict__ cur, int* __restrict__ pos,
                          int* __restrict__ srcs, int* __restrict__ dsts)
{
    int i = blockIdx.x * blockDim.x + threadIdx.x;
    if (i < N_EDGES) {
        int d = nbr[2 * i + 1];
        int p = off[d] + atomicAdd(&cur[d], 1);
        pos[i] = p;
        srcs[p] = nbr[2 * i];
        dsts[p] = d;
    }
}

// ---------------- weight fragment packing (conv layers + edge_w, once) ----------------
// m16n8k16 B-fragment: lane = 4*g + t holds for n-tile nt, k-step ks:
//   reg0 = half2( B[16ks+2t][nt*8+g], B[16ks+2t+1][nt*8+g] )
//   reg1 = half2( B[16ks+2t+8][nt*8+g], B[16ks+2t+9][nt*8+g] )
__global__ __launch_bounds__(256) void k_cvt(
    const float* __restrict__ w1, const float* __restrict__ w2,
    const float* __restrict__ ew,
    uint2* __restrict__ w1p, uint2* __restrict__ w2p, uint2* __restrict__ ewp)
{
    int i = blockIdx.x * 256 + threadIdx.x;
    if (i >= NLAYERS * 8192) return;
    int lane = i & 31;
    int t = lane & 3, g = lane >> 2;
    {   // W1P: B[k][n] = conv_w1[(128+k)*256 + n]; 8 ks x 32 nt
        int r = i >> 5;
        int nt = r & 31; r >>= 5;
        int ks = r & 7;  int layer = r >> 3;
        const float* W = w1 + (long)layer * 65536;
        int n = nt * 8 + g, k0 = ks * 16 + 2 * t;
        __half2 a = __floats2half2_rn(W[(128 + k0) * 256 + n], W[(129 + k0) * 256 + n]);
        __half2 b = __floats2half2_rn(W[(136 + k0) * 256 + n], W[(137 + k0) * 256 + n]);
        w1p[i] = make_uint2(*(uint32_t*)&a, *(uint32_t*)&b);
    }
    {   // W2P: B[k][n] = conv_w2[k*128 + n]; 16 ks x 16 nt
        int r = i >> 5;
        int nt = r & 15; r >>= 4;
        int ks = r & 15; int layer = r >> 4;
        const float* W = w2 + (long)layer * 32768;
        int n = nt * 8 + g, k0 = ks * 16 + 2 * t;
        __half2 a = __floats2half2_rn(W[k0 * 128 + n],       W[(k0 + 1) * 128 + n]);
        __half2 b = __floats2half2_rn(W[(k0 + 8) * 128 + n], W[(k0 + 9) * 128 + n]);
        w2p[i] = make_uint2(*(uint32_t*)&a, *(uint32_t*)&b);
    }
    if (i < 1536) {   // EWP: B[k][n] = edge_w[k*128+n], k<41 else 0; 3 ks x 16 nt
        int r = i >> 5;
        int nt = r & 15;
        int ks = r >> 4;         // 0..2
        int n = nt * 8 + g, k0 = ks * 16 + 2 * t;
        float v0 = (k0     < 41) ? ew[(k0    ) * 128 + n] : 0.0f;
        float v1 = (k0 + 1 < 41) ? ew[(k0 + 1) * 128 + n] : 0.0f;
        float v2 = (k0 + 8 < 41) ? ew[(k0 + 8) * 128 + n] : 0.0f;
        float v3 = (k0 + 9 < 41) ? ew[(k0 + 9) * 128 + n] : 0.0f;
        __half2 a = __floats2half2_rn(v0, v1);
        __half2 b = __floats2half2_rn(v2, v3);
        ewp[i] = make_uint2(*(uint32_t*)&a, *(uint32_t*)&b);
    }
}

// ---------------- edge embedding (HMMA): e[pos] = silu(nbr @ edge_w + b) ----------------
// 64-edge tiles, K=48 (padded), N=128. 256 threads = 8 warps (4 m-tiles x 2 n-halves).
__global__ __launch_bounds__(256) void k_edge_embed(
    const float* __restrict__ nbr, const uint2* __restrict__ EWP,
    const float* __restrict__ b, const int* __restrict__ pos, __half* __restrict__ e)
{
    __shared__ __align__(16) char sA[64 * 128];   // 64 rows x 64 halves (swizzled)
    __shared__ int spos[64];
    const int tid = threadIdx.x, lane = tid & 31, warp = tid >> 5;
    const int wm = (warp & 3) * 16, wnh = warp >> 2;
    const int g = lane >> 2, t = lane & 3;
    const uint32_t sbase = sptr(sA);
    const long e0 = (long)blockIdx.x * 64;

    if (tid < 64) spos[tid] = __ldg(&pos[e0 + tid]);
    #pragma unroll
    for (int p = 0; p < 16; p++) {
        int i = tid + p * 256;
        int row = i >> 6, c = i & 63;
        float v = (c < 41) ? __ldg(&nbr[(e0 + row) * 41 + c]) : 0.0f;
        __half hv = __float2half_rn(v);
        *(__half*)(sA + swz(row, c >> 3, 128) + ((c & 7) << 1)) = hv;
    }
    __syncthreads();

    float acc[8][4];
    #pragma unroll
    for (int nj = 0; nj < 8; nj++)
        #pragma unroll
        for (int q = 0; q < 4; q++) acc[nj][q] = 0.0f;

    #pragma unroll
    for (int ks = 0; ks < 3; ks++) {
        uint32_t af[4];
        ldsm_x4(af, sbase + swz(wm + (lane & 15), ks * 2 + (lane >> 4), 128));
        uint2 bf[8];
        const uint2* bp = EWP + (ks * 16 + wnh * 8) * 32 + lane;
        #pragma unroll
        for (int nj = 0; nj < 8; nj++) bf[nj] = __ldg(bp + nj * 32);
        #pragma unroll
        for (int nj = 0; nj < 8; nj++)
            mma_16816(acc[nj], af, (uint32_t*)&bf[nj]);
    }

    int r0 = wm + g, r1 = r0 + 8;
    long p0 = spos[r0], p1 = spos[r1];
    #pragma unroll
    for (int nj = 0; nj < 8; nj++) {
        int col = wnh * 64 + nj * 8 + 2 * t;
        float2 bb = __ldg((const float2*)(b + col));
        __half2 h0 = __floats2half2_rn(silu_f(acc[nj][0] + bb.x),
                                       silu_f(acc[nj][1] + bb.y));
        __half2 h1 = __floats2half2_rn(silu_f(acc[nj][2] + bb.x),
                                       silu_f(acc[nj][3] + bb.y));
        *(uint32_t*)(e + p0 * 128 + col) = *(uint32_t*)&h0;
        *(uint32_t*)(e + p1 * 128 + col) = *(uint32_t*)&h1;
    }
}

// ================= k_xw: XW = x @ W1a + b1 (HMMA, fp16 output) =================
#define XW_SE 0
#define XW_SW 32768
#define XW_SMEM 98304

template <int KR, int NC>
__device__ __forceinline__ void wload(char* sdst, const float* __restrict__ W, int tid) {
    const float4* wv = (const float4*)W;
    constexpr int NV = NC / 4;
    #pragma unroll 4
    for (int i = tid; i < KR * NV; i += 512) {
        int k = i / NV, n4 = (i % NV) * 4;
        float4 v = __ldg(&wv[i]);
        __half2 a = __floats2half2_rn(v.x, v.y);
        __half2 b = __floats2half2_rn(v.z, v.w);
        char* p = sdst + swz(k, n4 >> 3, NC * 2) + ((n4 & 7) << 1);
        *(uint32_t*)p = *(uint32_t*)&a;
        *(uint32_t*)(p + 4) = *(uint32_t*)&b;
    }
}

__global__ __launch_bounds__(512) void k_xw(
    const __half* __restrict__ Xh, const float* __restrict__ W1a,
    const float* __restrict__ b1, __half* __restrict__ XW)
{
    extern __shared__ char sm[];
    const int tid = threadIdx.x, lane = tid & 31, warp = tid >> 5;
    const int wm = (warp & 3) * 32, wn = warp >> 2;
    const int g = lane >> 2, t = lane & 3;
    const uint32_t sbase = sptr(sm);
    const long rowBase = (long)blockIdx.x * 128;

    wload<128, 256>(sm + XW_SW, W1a, tid);
    {
        int row = tid >> 2, cb = (tid & 3) * 4;
        long grow = rowBase + row;
        if (grow >= N_NODES) grow = N_NODES - 1;
        const uint4* p = (const uint4*)(Xh + grow * 128) + cb;
        #pragma unroll
        for (int j = 0; j < 4; j++)
            *(uint4*)(sm + XW_SE + swz(row, cb + j, 256)) = __ldg(p + j);
    }
    __syncthreads();

    float acc[2][8][4];
    #pragma unroll
    for (int mi = 0; mi < 2; mi++)
        #pragma unroll
        for (int nj = 0; nj < 8; nj++)
            #pragma unroll
            for (int q = 0; q < 4; q++) acc[mi][nj][q] = 0.0f;

    for (int ks = 0; ks < 8; ks++) {
        uint32_t af[2][4], bf[8][2];
        #pragma unroll
        for (int mi = 0; mi < 2; mi++)
            ldsm_x4(af[mi], sbase + XW_SE +
                    swz(wm + mi * 16 + (lane & 15), ks * 2 + (lane >> 4), 256));
        #pragma unroll
        for (int np = 0; np < 4; np++) {
            uint32_t r4[4];
            ldsm_x4_t(r4, sbase + XW_SW +
                      swz(ks * 16 + (lane & 15), wn * 8 + np * 2 + (lane >> 4), 512));
            bf[np * 2 + 0][0] = r4[0]; bf[np * 2 + 0][1] = r4[1];
            bf[np * 2 + 1][0] = r4[2]; bf[np * 2 + 1][1] = r4[3];
        }
        #pragma unroll
        for (int mi = 0; mi < 2; mi++)
            #pragma unroll
            for (int nj = 0; nj < 8; nj++)
                mma_16816(acc[mi][nj], af[mi], bf[nj]);
    }

    #pragma unroll
    for (int mi = 0; mi < 2; mi++) {
        long g0 = rowBase + wm + mi * 16 + g, g1 = g0 + 8;
        #pragma unroll
        for (int nj = 0; nj < 8; nj++) {
            int col = wn * 64 + nj * 8 + 2 * t;
            float2 bb = *(const float2*)(b1 + col);
            if (g0 < N_NODES) {
                __half2 h = __floats2half2_rn(acc[mi][nj][0] + bb.x, acc[mi][nj][1] + bb.y);
                *(uint32_t*)(XW + g0 * 256 + col) = *(uint32_t*)&h;
            }
            if (g1 < N_NODES) {
                __half2 h = __floats2half2_rn(acc[mi][nj][2] + bb.x, acc[mi][nj][3] + bb.y);
                *(uint32_t*)(XW + g1 * 256 + col) = *(uint32_t*)&h;
            }
        }
    }
}

// ================= k_conv: 32-edge tiles, 256 threads, 3 CTAs/SM =================
#define CE 0
#define CM 8192
#define CI 24576
#define CONV_SMEM 24832

__global__ __launch_bounds__(256, 3) void k_conv(
    const __half* __restrict__ E, const uint2* __restrict__ W1P,
    const uint2* __restrict__ W2P, const __half* __restrict__ XW,
    const float* __restrict__ b2, const int* __restrict__ srcs,
    const int* __restrict__ dsts, float* __restrict__ aggr)
{
    extern __shared__ char sm[];
    const int tid = threadIdx.x, lane = tid & 31, wn = tid >> 5;   // 8 warps
    const int g = lane >> 2, t = lane & 3;
    const uint32_t sbase = sptr(sm);
    int* sSrc = (int*)(sm + CI);
    int* sDst = sSrc + 32;
    const long ebase = (long)blockIdx.x * TEDG;

    // group A: indices
    if (tid < 8) CP_ASYNC16(sbase + CI + tid * 16, srcs + ebase + tid * 4);
    else if (tid < 16) CP_ASYNC16(sbase + CI + 128 + (tid - 8) * 16, dsts + ebase + (tid - 8) * 4);
    CP_COMMIT();
    // group B: E tile (32x128 f16)
    #pragma unroll
    for (int p = 0; p < 2; p++) {
        int i = tid + p * 256;
        int row = i >> 4, c8 = i & 15;
        CP_ASYNC16(sbase + CE + swz(row, c8, 256), E + (ebase + row) * 128 + c8 * 8);
    }
    CP_COMMIT();
    CP_WAIT1();        // idx done (E may be pending)
    __syncthreads();   // S1: sSrc visible

    // group C: XW gather (32 rows x 256 f16 = 16KB)
    #pragma unroll
    for (int p = 0; p < 4; p++) {
        int i = tid + p * 256;
        int row = i >> 5, c8 = i & 31;
        CP_ASYNC16(sbase + CM + swz(row, c8, 512),
                   XW + (long)sSrc[row] * 256 + c8 * 8);
    }
    CP_COMMIT();
    CP_WAIT1();        // E done (XW may be pending)
    __syncthreads();   // S2: E visible

    // ---- phase 1: D1 = E @ W1b  (32 x 256, K=128) ----
    float acc[2][4][4];
    #pragma unroll
    for (int mi = 0; mi < 2; mi++)
        #pragma unroll
        for (int nj = 0; nj < 4; nj++)
            #pragma unroll
            for (int q = 0; q < 4; q++) acc[mi][nj][q] = 0.0f;

    #pragma unroll
    for (int ks = 0; ks < 8; ks++) {
        uint32_t af[2][4];
        #pragma unroll
        for (int mi = 0; mi < 2; mi++)
            ldsm_x4(af[mi], sbase + CE +
                    swz(mi * 16 + (lane & 15), ks * 2 + (lane >> 4), 256));
        uint2 bf[4];
        const uint2* bp = W1P + (ks * 32 + wn * 4) * 32 + lane;
        #pragma unroll
        for (int nj = 0; nj < 4; nj++) bf[nj] = __ldg(bp + nj * 32);
        #pragma unroll
        for (int mi = 0; mi < 2; mi++)
            #pragma unroll
            for (int nj = 0; nj < 4; nj++)
                mma_16816(acc[mi][nj], af[mi], (uint32_t*)&bf[nj]);
    }
    CP_WAIT0();
    __syncthreads();   // S3: XW staged, phase-1 E reads done

    // ---- epilogue 1: M1 = silu(D1 + XW_staged), in-place fp16 in CM ----
    #pragma unroll
    for (int mi = 0; mi < 2; mi++) {
        int r0 = mi * 16 + g, r1 = r0 + 8;
        #pragma unroll
        for (int nj = 0; nj < 4; nj++) {
            int col = wn * 32 + nj * 8 + 2 * t;
            uint32_t a0o = CM + swz(r0, col >> 3, 512) + ((col & 7) << 1);
            uint32_t a1o = CM + swz(r1, col >> 3, 512) + ((col & 7) << 1);
            float2 f0 = __half22float2(*(__half2*)(sm + a0o));
            float2 f1 = __half22float2(*(__half2*)(sm + a1o));
            __half2 h0 = __floats2half2_rn(silu_f(acc[mi][nj][0] + f0.x),
                                           silu_f(acc[mi][nj][1] + f0.y));
            __half2 h1 = __floats2half2_rn(silu_f(acc[mi][nj][2] + f1.x),
                                           silu_f(acc[mi][nj][3] + f1.y));
            *(__half2*)(sm + a0o) = h0;
            *(__half2*)(sm + a1o) = h1;
        }
    }
    __syncthreads();   // S4: M1 complete

    // ---- phase 2: D2 = M1 @ W2  (32 x 128, K=256) ----
    float ac2[2][2][4];
    #pragma unroll
    for (int mi = 0; mi < 2; mi++)
        #pragma unroll
        for (int nj = 0; nj < 2; nj++)
            #pragma unroll
            for (int q = 0; q < 4; q++) ac2[mi][nj][q] = 0.0f;

    #pragma unroll
    for (int ks = 0; ks < 16; ks++) {
        uint32_t af[2][4];
        #pragma unroll
        for (int mi = 0; mi < 2; mi++)
            ldsm_x4(af[mi], sbase + CM +
                    swz(mi * 16 + (lane & 15), ks * 2 + (lane >> 4), 512));
        uint2 bf[2];
        const uint2* bp = W2P + (ks * 16 + wn * 2) * 32 + lane;
        #pragma unroll
        for (int nj = 0; nj < 2; nj++) bf[nj] = __ldg(bp + nj * 32);
        #pragma unroll
        for (int mi = 0; mi < 2; mi++)
            #pragma unroll
            for (int nj = 0; nj < 2; nj++)
                mma_16816(ac2[mi][nj], af[mi], (uint32_t*)&bf[nj]);
    }

    // ---- epilogue 2a: stage silu(D2 + b2) fp16 into CE (dead E region) ----
    #pragma unroll
    for (int mi = 0; mi < 2; mi++) {
        int r0 = mi * 16 + g, r1 = r0 + 8;
        #pragma unroll
        for (int nj = 0; nj < 2; nj++) {
            int col = wn * 16 + nj * 8 + 2 * t;
            float2 bb = __ldg((const float2*)(b2 + col));
            __half2 h0 = __floats2half2_rn(silu_f(ac2[mi][nj][0] + bb.x),
                                           silu_f(ac2[mi][nj][1] + bb.y));
            __half2 h1 = __floats2half2_rn(silu_f(ac2[mi][nj][2] + bb.x),
                                           silu_f(ac2[mi][nj][3] + bb.y));
            *(__half2*)(sm + CE + swz(r0, col >> 3, 256) + ((col & 7) << 1)) = h0;
            *(__half2*)(sm + CE + swz(r1, col >> 3, 256) + ((col & 7) << 1)) = h1;
        }
    }
    __syncthreads();   // S5

    // ---- epilogue 2b: segmented reduction over dst-sorted rows ----
    {
        int c = tid & 63;
        int q = tid >> 6;
        int col = 2 * c;
        float ax = 0.0f, ay = 0.0f;
        int prev = sDst[8 * q];
        #pragma unroll
        for (int r8 = 0; r8 < 8; r8++) {
            int r = 8 * q + r8;
            int d = sDst[r];
            if (d != prev) {
                red2(aggr + (long)prev * 128 + col, ax, ay);
                ax = 0.0f; ay = 0.0f; prev = d;
            }
            uint32_t hv = *(uint32_t*)(sm + CE + swz(r, col >> 3, 256) +
                                       ((col & 7) << 1));
            float2 v = __half22float2(*(__half2*)&hv);
            ax += v.x; ay += v.y;
        }
        red2(aggr + (long)prev * 128 + col, ax, ay);
    }
}

// ---------------- warp-per-node LN: x = LN(x + aggr/cnt), zero aggr, emit fp16 ----------------
__global__ __launch_bounds__(128) void k_ln_aggr(
    float* __restrict__ x, __half* __restrict__ xh, float* __restrict__ aggr,
    const int* __restrict__ deg, const float* __restrict__ lg,
    const float* __restrict__ lb)
{
    const int lane = threadIdx.x & 31, w = threadIdx.x >> 5;
    const long n = (long)blockIdx.x * 4 + w;
    const int c0 = lane * 4;
    float cnt = (float)__ldg(&deg[n]); if (cnt < 1.0f) cnt = 1.0f;
    float inv = __fdividef(1.0f, cnt);
    float4 xv = *(float4*)(x + n * 128 + c0);
    float4 av = *(float4*)(aggr + n * 128 + c0);
    *(float4*)(aggr + n * 128 + c0) = make_float4(0.f, 0.f, 0.f, 0.f);
    float4 tv;
    tv.x = xv.x + av.x * inv; tv.y = xv.y + av.y * inv;
    tv.z = xv.z + av.z * inv; tv.w = xv.w + av.w * inv;
    float s = tv.x + tv.y + tv.z + tv.w;
    float s2 = tv.x * tv.x + tv.y * tv.y + tv.z * tv.z + tv.w * tv.w;
    #pragma unroll
    for (int o = 16; o > 0; o >>= 1) {
        s  += __shfl_xor_sync(0xffffffffu, s,  o);
        s2 += __shfl_xor_sync(0xffffffffu, s2, o);
    }
    float mean = s * (1.0f / 128.0f);
    float var  = s2 * (1.0f / 128.0f) - mean * mean;
    float rstd = rsqrtf(var + 1e-5f);
    float4 gv = *(const float4*)(lg + c0);
    float4 bv = *(const float4*)(lb + c0);
    float4 ov;
    ov.x = (tv.x - mean) * rstd * gv.x + bv.x;
    ov.y = (tv.y - mean) * rstd * gv.y + bv.y;
    ov.z = (tv.z - mean) * rstd * gv.z + bv.z;
    ov.w = (tv.w - mean) * rstd * gv.w + bv.w;
    *(float4*)(x + n * 128 + c0) = ov;
    __half2 h0 = __floats2half2_rn(ov.x, ov.y);
    __half2 h1 = __floats2half2_rn(ov.z, ov.w);
    uint2 hp = make_uint2(*(uint32_t*)&h0, *(uint32_t*)&h1);
    *(uint2*)(xh + n * 128 + c0) = hp;
}

// ---------------- graph pooling ----------------
__global__ __launch_bounds__(128) void k_pool(
    const float* __restrict__ x, const int* __restrict__ bm,
    float* __restrict__ pool, float* __restrict__ gcnt)
{
    int n = blockIdx.x, h = threadIdx.x;
    int g = bm[n];
    atomicAdd(&pool[g * 128 + h], x[n * 128 + h]);
    if (h == 0) atomicAdd(&gcnt[g], 1.0f);
}

// ---------------- output MLP ----------------
__global__ __launch_bounds__(128) void k_head(
    const float* __restrict__ pool, const float* __restrict__ gcnt,
    const float* __restrict__ w1, const float* __restrict__ b1,
    const float* __restrict__ w2, const float* __restrict__ b2,
    const float* __restrict__ w3, const float* __restrict__ b3,
    float* __restrict__ out)
{
    __shared__ float c[128], h1[128], h2[64];
    int g = blockIdx.x, h = threadIdx.x;
    float gc = gcnt[g]; if (gc < 1.0f) gc = 1.0f;
    c[h] = pool[g * 128 + h] / gc;
    __syncthreads();
    float a = b1[h];
    #pragma unroll 8
    for (int k = 0; k < 128; k++) a = fmaf(c[k], __ldg(&w1[k * 128 + h]), a);
    h1[h] = silu_f(a);
    __syncthreads();
    if (h < 64) {
        float a2 = b2[h];
        #pragma unroll 8
        for (int k = 0; k < 128; k++) a2 = fmaf(h1[k], __ldg(&w2[k * 64 + h]), a2);
        h2[h] = silu_f(a2);
    }
    __syncthreads();
    if (h < 3) {
        float a3 = b3[h];
        #pragma unroll
        for (int k = 0; k < 64; k++) a3 = fmaf(h2[k], __ldg(&w3[k * 3 + h]), a3);
        out[g * 3 + h] = a3;
    }
}

static inline int ceildiv(int a, int b) { return (a + b - 1) / b; }

extern "C" void kernel_launch(void* const* d_in, const int* in_sizes, int n_in,
                              void* d_out, int out_size)
{
    const float* atom_fea = (const float*)d_in[0];
    const float* nbr_fea  = (const float*)d_in[1];
    const int*   nbr_idx  = (const int*)  d_in[2];
    const int*   batch    = (const int*)  d_in[3];
    const float* emb_w    = (const float*)d_in[4];
    const float* emb_b    = (const float*)d_in[5];
    const float* emb_ln_g = (const float*)d_in[6];
    const float* emb_ln_b = (const float*)d_in[7];
    const float* edge_w   = (const float*)d_in[8];
    const float* edge_b   = (const float*)d_in[9];
    const float* conv_w1  = (const float*)d_in[10];
    const float* conv_b1  = (const float*)d_in[11];
    const float* conv_w2  = (const float*)d_in[12];
    const float* conv_b2  = (const float*)d_in[13];
    const float* ln_g     = (const float*)d_in[14];
    const float* ln_b     = (const float*)d_in[15];
    const float* out_w1   = (const float*)d_in[16];
    const float* out_b1   = (const float*)d_in[17];
    const float* out_w2   = (const float*)d_in[18];
    const float* out_b2   = (const float*)d_in[19];
    const float* out_w3   = (const float*)d_in[20];
    const float* out_b3   = (const float*)d_in[21];
    float* out = (float*)d_out;

    float *x, *aggr, *pool, *gcnt;
    __half *xh, *eh, *xw;
    uint2 *w1p, *w2p, *ewp;
    int *deg, *cur, *off, *pos, *srcs, *dsts;
    cudaGetSymbolAddress((void**)&x,    g_x);
    cudaGetSymbolAddress((void**)&xh,   g_xh);
    cudaGetSymbolAddress((void**)&eh,   g_eh);
    cudaGetSymbolAddress((void**)&xw,   g_xw);
    cudaGetSymbolAddress((void**)&aggr, g_aggr);
    cudaGetSymbolAddress((void**)&pool, g_pool);
    cudaGetSymbolAddress((void**)&gcnt, g_gcnt);
    cudaGetSymbolAddress((void**)&w1p,  g_w1p);
    cudaGetSymbolAddress((void**)&w2p,  g_w2p);
    cudaGetSymbolAddress((void**)&ewp,  g_ewp);
    cudaGetSymbolAddress((void**)&deg,  g_deg);
    cudaGetSymbolAddress((void**)&cur,  g_cur);
    cudaGetSymbolAddress((void**)&off,  g_off);
    cudaGetSymbolAddress((void**)&pos,  g_pos);
    cudaGetSymbolAddress((void**)&srcs, g_srcs);
    cudaGetSymbolAddress((void**)&dsts, g_dsts);

    static int attr_set = 0;
    if (!attr_set) {
        cudaFuncSetAttribute(k_xw,
                             cudaFuncAttributeMaxDynamicSharedMemorySize, XW_SMEM);
        attr_set = 1;
    }

    cudaMemsetAsync(deg,  0, N_NODES * sizeof(int), 0);
    cudaMemsetAsync(cur,  0, N_NODES * sizeof(int), 0);
    cudaMemsetAsync(aggr, 0, N_NODES * 128 * sizeof(float), 0);
    cudaMemsetAsync(pool, 0, N_GRAPHS * 128 * sizeof(float), 0);
    cudaMemsetAsync(gcnt, 0, N_GRAPHS * sizeof(float), 0);

    k_node_embed<<<N_NODES, 128>>>(atom_fea, emb_w, emb_b, emb_ln_g, emb_ln_b, x, xh);
    k_deg<<<ceildiv(N_EDGES, 256), 256>>>(nbr_idx, deg, N_EDGES);
    k_cvt<<<ceildiv(NLAYERS * 8192, 256), 256>>>(conv_w1, conv_w2, edge_w,
                                                 w1p, w2p, ewp);
    k_scan<<<1, 1024>>>(deg, off);
    k_scatter<<<ceildiv(N_EDGES, 256), 256>>>(nbr_idx, off, cur, pos, srcs, dsts);
    k_edge_embed<<<N_EDGES / 64, 256>>>(nbr_fea, ewp, edge_b, pos, eh);

    for (int i = 0; i < NLAYERS; i++) {
        const float* W1a = conv_w1 + (long)i * 256 * 256;
        const float* b1  = conv_b1 + (long)i * 256;
        const float* b2  = conv_b2 + (long)i * 128;

        k_xw<<<ceildiv(N_NODES, 128), 512, XW_SMEM>>>(xh, W1a, b1, xw);
        k_conv<<<N_UNITS, 256, CONV_SMEM>>>(eh, w1p + (long)i * 8192,
                                            w2p + (long)i * 8192, xw, b2,
                                            srcs, dsts, aggr);
        k_ln_aggr<<<ceildiv(N_NODES, 4), 128>>>(x, xh, aggr, deg,
                                                ln_g + i * 128, ln_b + i * 128);
    }

    k_pool<<<N_NODES, 128>>>(x, batch, pool, gcnt);
    k_head<<<N_GRAPHS, 128>>>(pool, gcnt, out_w1, out_b1, out_w2, out_b2,
                              out_w3, out_b3, out);
    (void)in_sizes; (void)n_in; (void)out_size;
}